// round 8
// baseline (speedup 1.0000x reference)
#include <cuda_runtime.h>
#include <math.h>

#define T_TOK 512
#define CHUNK 64
#define NCHUNK 8
#define HH 28
#define WW 28
#define CC 4
#define DM 3136
#define DH 512

#define FSEG 49    // fwd/dadh split-K segments (k = 64 each)
#define PSEG 8     // pred split-K segments (k = 64 each)
#define GSEG 8     // kgram split-K segments (k = 392 each)

typedef unsigned long long ull;

// ---------------- f32x2 helpers ----------------
__device__ __forceinline__ ull pk2(float lo, float hi) {
    ull r; asm("mov.b64 %0, {%1,%2};" : "=l"(r) : "f"(lo), "f"(hi)); return r;
}
__device__ __forceinline__ void upk2(float& lo, float& hi, ull v) {
    asm("mov.b64 {%0,%1}, %2;" : "=f"(lo), "=f"(hi) : "l"(v));
}
#define FFMA2(d, a, b) asm("fma.rn.f32x2 %0, %1, %2, %0;" : "+l"(d) : "l"(a), "l"(b))

// ---------------- device scratch ----------------
__device__ __align__(16) float g_nk[T_TOK * DM];
__device__ __align__(16) float g_nv[T_TOK * DM];
__device__ __align__(16) float g_W1[DM * DH];
__device__ __align__(16) float g_W2[DH * DM];
__device__ __align__(16) float g_b1[DH];
__device__ __align__(16) float g_b2[DM];
__device__ __align__(16) float g_H[CHUNK * DH];
__device__ __align__(16) float g_A[CHUNK * DH];
__device__ __align__(16) float g_A2[CHUNK * DH];
__device__ __align__(16) float g_dpred[CHUNK * DM];
__device__ __align__(16) float g_dh[CHUNK * DH];
__device__ __align__(16) float g_G[CHUNK * CHUNK];
__device__ __align__(16) float g_fpart[FSEG * CHUNK * DH];    // 6.4 MB (fwd & dadh partials)
__device__ __align__(16) float g_ppart[PSEG * CHUNK * DM];    // 6.4 MB (pred partials)
__device__ __align__(16) float g_gpart[GSEG * CHUNK * CHUNK];

// ---------------- math helpers ----------------
__device__ __forceinline__ float gelu_f(float x) {
    const float c = 0.7978845608028654f, a = 0.044715f;
    float u = c * (x + a * x * x * x);
    return 0.5f * x * (1.0f + tanhf(u));
}
__device__ __forceinline__ float dgelu_f(float x) {
    const float c = 0.7978845608028654f, a = 0.044715f;
    float x2 = x * x;
    float u = c * (x + a * x * x2);
    float th = tanhf(u);
    return 0.5f * (1.0f + th) + 0.5f * x * (1.0f - th * th) * c * (1.0f + 3.0f * a * x2);
}

// ---------------- prologue: conv3x3+rmsnorm (blocks < 1568) and param copy ----------------
__global__ void prologue_kernel(const float* __restrict__ x,
                                const float* __restrict__ wk, const float* __restrict__ bk,
                                const float* __restrict__ wv, const float* __restrict__ bv,
                                const float* __restrict__ sk, const float* __restrict__ sv,
                                const float* __restrict__ W1, const float* __restrict__ b1,
                                const float* __restrict__ W2, const float* __restrict__ b2) {
    int tid = threadIdx.x;
    if (blockIdx.x < 1568) {
        __shared__ float swk[144], swv[144], sbk[4], sbv[4], ssk[4], ssv[4];
        if (tid < 144) { swk[tid] = wk[tid]; swv[tid] = wv[tid]; }
        if (tid < 4) { sbk[tid] = bk[tid]; sbv[tid] = bv[tid]; ssk[tid] = sk[tid]; ssv[tid] = sv[tid]; }
        __syncthreads();
        int idx = blockIdx.x * 256 + tid;   // 401408 exact
        int w = idx % WW;
        int h = (idx / WW) % HH;
        int t = idx / (HH * WW);
        float acck[4], accv[4];
#pragma unroll
        for (int o = 0; o < 4; o++) { acck[o] = sbk[o]; accv[o] = sbv[o]; }
        const float* xt = x + t * (CC * HH * WW);
#pragma unroll
        for (int kh = 0; kh < 3; kh++) {
            int hy = h + kh - 1;
            if (hy < 0 || hy >= HH) continue;
#pragma unroll
            for (int kw = 0; kw < 3; kw++) {
                int wx = w + kw - 1;
                if (wx < 0 || wx >= WW) continue;
                int wbase = (kh * 3 + kw) * 16;
#pragma unroll
                for (int ci = 0; ci < 4; ci++) {
                    float xv = xt[ci * (HH * WW) + hy * WW + wx];
#pragma unroll
                    for (int o = 0; o < 4; o++) {
                        acck[o] += xv * swk[wbase + ci * 4 + o];
                        accv[o] += xv * swv[wbase + ci * 4 + o];
                    }
                }
            }
        }
        float msk = 0.f, msv = 0.f;
#pragma unroll
        for (int o = 0; o < 4; o++) { msk += acck[o] * acck[o]; msv += accv[o] * accv[o]; }
        float ik = rsqrtf(msk * 0.25f + 1e-6f);
        float iv = rsqrtf(msv * 0.25f + 1e-6f);
        int base = t * DM + (h * WW + w) * CC;
#pragma unroll
        for (int o = 0; o < 4; o++) {
            g_nk[base + o] = acck[o] * ik * ssk[o];
            g_nv[base + o] = accv[o] * iv * ssv[o];
        }
    } else {
        int i = (blockIdx.x - 1568) * 256 + tid;   // 131072 threads
        for (int k = i; k < DM * DH; k += 131072) { g_W1[k] = W1[k]; g_W2[k] = W2[k]; }
        if (i < DH) g_b1[i] = b1[i];
        if (i < DM) g_b2[i] = b2[i];
    }
}

// ---------------- fwd split-K GEMM + kgram ----------------
// blocks [0,196): fpart[seg][m][n] = sum_{k in seg64} K[m,k]*W1[k,n]  (4m x 8n, f32x2)
// blocks [196,324): gpart[seg][m][n] = sum_{k in seg392} K[m,k]*K[n,k]
__global__ void __launch_bounds__(256) fwd_kgram_kernel(const float* __restrict__ Kc) {
    if (blockIdx.x < 196) {
        int f = blockIdx.x * 256 + threadIdx.x;
        int n0 = (f & 63) * 8;
        int m0 = ((f >> 6) & 15) * 4;
        int seg = f >> 10;                 // 0..48
        int k0 = seg * 64;
        const float* K = Kc + m0 * DM;
        const float* Wp = g_W1 + n0;
        ull acc[4][4];
#pragma unroll
        for (int i = 0; i < 4; i++)
#pragma unroll
            for (int j = 0; j < 4; j++) acc[i][j] = 0ULL;
#pragma unroll 8
        for (int k = k0; k < k0 + 64; k++) {
            ulonglong2 wa = *reinterpret_cast<const ulonglong2*>(Wp + (size_t)k * DH);
            ulonglong2 wb = *reinterpret_cast<const ulonglong2*>(Wp + (size_t)k * DH + 4);
            ull bv[4] = {wa.x, wa.y, wb.x, wb.y};
            float x0 = K[k], x1 = K[DM + k], x2 = K[2 * DM + k], x3 = K[3 * DM + k];
            ull av[4] = {pk2(x0, x0), pk2(x1, x1), pk2(x2, x2), pk2(x3, x3)};
#pragma unroll
            for (int i = 0; i < 4; i++)
#pragma unroll
                for (int j = 0; j < 4; j++) FFMA2(acc[i][j], av[i], bv[j]);
        }
        float* P = g_fpart + seg * (CHUNK * DH) + m0 * DH + n0;
#pragma unroll
        for (int i = 0; i < 4; i++) {
            float o0, o1, o2, o3, o4, o5, o6, o7;
            upk2(o0, o1, acc[i][0]); upk2(o2, o3, acc[i][1]);
            upk2(o4, o5, acc[i][2]); upk2(o6, o7, acc[i][3]);
            *reinterpret_cast<float4*>(P + i * DH)     = make_float4(o0, o1, o2, o3);
            *reinterpret_cast<float4*>(P + i * DH + 4) = make_float4(o4, o5, o6, o7);
        }
    } else {
        // kgram: gpart[seg][m][n] = sum over 392 k of K[m,k]*K[n,k]
        int t = (blockIdx.x - 196) * 256 + threadIdx.x;   // 32768
        int seg = t >> 12;                 // 0..7
        int o = t & 4095;
        int m = o >> 6;
        int n = o & 63;
        int kbase = seg * 392;
        const ull* pa = reinterpret_cast<const ull*>(Kc + m * DM + kbase);
        const ull* pb = reinterpret_cast<const ull*>(Kc + n * DM + kbase);
        ull acc2 = 0ULL;
#pragma unroll 8
        for (int k2 = 0; k2 < 196; k2++) FFMA2(acc2, pa[k2], pb[k2]);
        float lo, hi;
        upk2(lo, hi, acc2);
        g_gpart[seg * 4096 + o] = lo + hi;
    }
}

// ---------------- reduce fwd partials -> H, A ; and G ----------------
__global__ void reduce1G_kernel() {
    int f = blockIdx.x * 256 + threadIdx.x;   // 36 blocks = 9216 (8192 + 1024)
    if (f < 8192) {
        int idx4 = f * 4;
        float4 s = *reinterpret_cast<const float4*>(&g_b1[idx4 & (DH - 1)]);
#pragma unroll
        for (int sg = 0; sg < FSEG; sg++) {
            float4 p = *reinterpret_cast<const float4*>(&g_fpart[sg * (CHUNK * DH) + idx4]);
            s.x += p.x; s.y += p.y; s.z += p.z; s.w += p.w;
        }
        *reinterpret_cast<float4*>(&g_H[idx4]) = s;
        *reinterpret_cast<float4*>(&g_A[idx4]) =
            make_float4(gelu_f(s.x), gelu_f(s.y), gelu_f(s.z), gelu_f(s.w));
    } else if (f < 9216) {
        int idx4 = (f - 8192) * 4;
        float4 s = make_float4(0.f, 0.f, 0.f, 0.f);
#pragma unroll
        for (int sg = 0; sg < GSEG; sg++) {
            float4 p = *reinterpret_cast<const float4*>(&g_gpart[sg * 4096 + idx4]);
            s.x += p.x; s.y += p.y; s.z += p.z; s.w += p.w;
        }
        *reinterpret_cast<float4*>(&g_G[idx4]) = s;
    }
}

// ---------------- pred split-K GEMM: ppart[seg][m][d] = sum_{j in seg64} A[m,j]*W2[j,d] ----------------
__global__ void __launch_bounds__(256) pred_gemm_kernel(const float* __restrict__ Asrc) {
    int f = blockIdx.x * 256 + threadIdx.x;    // 196 blocks = 50176
    int d0 = (f % 392) * 8;
    int m0 = ((f / 392) & 15) * 4;
    int seg = f / 6272;                        // 0..7
    int j0 = seg * 64;
    const float* A0 = Asrc + m0 * DH;
    const float* Wp = g_W2 + d0;
    ull acc[4][4];
#pragma unroll
    for (int i = 0; i < 4; i++)
#pragma unroll
        for (int j = 0; j < 4; j++) acc[i][j] = 0ULL;
#pragma unroll 8
    for (int j = j0; j < j0 + 64; j++) {
        ulonglong2 wa = *reinterpret_cast<const ulonglong2*>(Wp + (size_t)j * DM);
        ulonglong2 wb = *reinterpret_cast<const ulonglong2*>(Wp + (size_t)j * DM + 4);
        ull bv[4] = {wa.x, wa.y, wb.x, wb.y};
        float a0 = A0[j], a1 = A0[DH + j], a2 = A0[2 * DH + j], a3 = A0[3 * DH + j];
        ull av[4] = {pk2(a0, a0), pk2(a1, a1), pk2(a2, a2), pk2(a3, a3)};
#pragma unroll
        for (int i = 0; i < 4; i++)
#pragma unroll
            for (int jj = 0; jj < 4; jj++) FFMA2(acc[i][jj], av[i], bv[jj]);
    }
    float* P = g_ppart + seg * (CHUNK * DM) + m0 * DM + d0;
#pragma unroll
    for (int i = 0; i < 4; i++) {
        float o0, o1, o2, o3, o4, o5, o6, o7;
        upk2(o0, o1, acc[i][0]); upk2(o2, o3, acc[i][1]);
        upk2(o4, o5, acc[i][2]); upk2(o6, o7, acc[i][3]);
        *reinterpret_cast<float4*>(P + i * DM)     = make_float4(o0, o1, o2, o3);
        *reinterpret_cast<float4*>(P + i * DM + 4) = make_float4(o4, o5, o6, o7);
    }
}

// ---------------- reduce pred partials: mode0 -> dpred, mode1 -> out ----------------
__global__ void reduce2_kernel(int c, int mode, float* __restrict__ out) {
    int f = blockIdx.x * 256 + threadIdx.x;   // 196 blocks = 50176
    int idx4 = f * 4;
    int d0 = idx4 % DM;
    float4 s = *reinterpret_cast<const float4*>(&g_b2[d0]);
#pragma unroll
    for (int sg = 0; sg < PSEG; sg++) {
        float4 p = *reinterpret_cast<const float4*>(&g_ppart[sg * (CHUNK * DM) + idx4]);
        s.x += p.x; s.y += p.y; s.z += p.z; s.w += p.w;
    }
    if (mode == 0) {
        float4 v = *reinterpret_cast<const float4*>(&g_nv[c * (CHUNK * DM) + idx4]);
        *reinterpret_cast<float4*>(&g_dpred[idx4]) =
            make_float4(2.f * (s.x - v.x), 2.f * (s.y - v.y), 2.f * (s.z - v.z), 2.f * (s.w - v.w));
    } else {
        *reinterpret_cast<float4*>(&out[c * (CHUNK * DM) + idx4]) = s;
    }
}

// ---------------- dadh split-K GEMM: fpart[seg][m][j] = sum_{d in seg64} dpred[m,d]*W2[j,d] ----------------
__global__ void __launch_bounds__(256) dadh_gemm_kernel() {
    int f = blockIdx.x * 256 + threadIdx.x;    // 196 blocks = 50176
    int n0 = (f & 63) * 8;                     // j tile
    int m0 = ((f >> 6) & 15) * 4;
    int seg = f >> 10;                         // 0..48
    int k0 = seg * 64;
    const float* A0 = g_dpred + m0 * DM + k0;
    const float* B0 = g_W2 + n0 * DM + k0;
    ull acc[4][8];
#pragma unroll
    for (int i = 0; i < 4; i++)
#pragma unroll
        for (int j = 0; j < 8; j++) acc[i][j] = 0ULL;
#pragma unroll 4
    for (int k4 = 0; k4 < 16; k4++) {
        ulonglong2 a[4];
#pragma unroll
        for (int i = 0; i < 4; i++)
            a[i] = *reinterpret_cast<const ulonglong2*>(A0 + i * DM + k4 * 4);
#pragma unroll
        for (int j = 0; j < 8; j++) {
            ulonglong2 b = *reinterpret_cast<const ulonglong2*>(B0 + j * DM + k4 * 4);
#pragma unroll
            for (int i = 0; i < 4; i++) {
                FFMA2(acc[i][j], a[i].x, b.x);
                FFMA2(acc[i][j], a[i].y, b.y);
            }
        }
    }
    float* P = g_fpart + seg * (CHUNK * DH) + m0 * DH + n0;
#pragma unroll
    for (int i = 0; i < 4; i++) {
        float o[8];
#pragma unroll
        for (int j = 0; j < 8; j++) {
            float lo, hi; upk2(lo, hi, acc[i][j]);
            o[j] = lo + hi;
        }
        *reinterpret_cast<float4*>(P + i * DH)     = make_float4(o[0], o[1], o[2], o[3]);
        *reinterpret_cast<float4*>(P + i * DH + 4) = make_float4(o[4], o[5], o[6], o[7]);
    }
}

// ---------------- reduce dadh partials -> dh (with dgelu) ----------------
__global__ void reduceDh_kernel() {
    int f = blockIdx.x * 256 + threadIdx.x;   // 32 blocks = 8192
    int idx4 = f * 4;
    float4 s = make_float4(0.f, 0.f, 0.f, 0.f);
#pragma unroll
    for (int sg = 0; sg < FSEG; sg++) {
        float4 p = *reinterpret_cast<const float4*>(&g_fpart[sg * (CHUNK * DH) + idx4]);
        s.x += p.x; s.y += p.y; s.z += p.z; s.w += p.w;
    }
    float4 h = *reinterpret_cast<const float4*>(&g_H[idx4]);
    *reinterpret_cast<float4*>(&g_dh[idx4]) =
        make_float4(s.x * dgelu_f(h.x), s.y * dgelu_f(h.y), s.z * dgelu_f(h.z), s.w * dgelu_f(h.w));
}

// ---------------- fused: W2/W1/bias updates + recall activation A2 (via Gram) ----------------
__global__ void __launch_bounds__(256) update_recall_kernel(const float* __restrict__ Kc, float wgt) {
    int f = blockIdx.x * 256 + threadIdx.x;
    if (f < 50176) {
        // W2[j,d] -= w * sum_m A[m,j] * dpred[m,d]
        int d0 = (f % 784) * 4;
        int j0 = (f / 784) * 8;
        ull acc[8][2];
#pragma unroll
        for (int i = 0; i < 8; i++) { acc[i][0] = 0ULL; acc[i][1] = 0ULL; }
#pragma unroll 4
        for (int m = 0; m < CHUNK; m++) {
            ulonglong2 p = *reinterpret_cast<const ulonglong2*>(g_dpred + m * DM + d0);
            const float* Am = g_A + m * DH + j0;
#pragma unroll
            for (int i = 0; i < 8; i++) {
                ull a2 = pk2(Am[i], Am[i]);
                FFMA2(acc[i][0], a2, p.x);
                FFMA2(acc[i][1], a2, p.y);
            }
        }
#pragma unroll
        for (int i = 0; i < 8; i++) {
            float* Wp = g_W2 + (j0 + i) * DM + d0;
            float4 old = *reinterpret_cast<float4*>(Wp);
            float l0, h0, l1, h1;
            upk2(l0, h0, acc[i][0]); upk2(l1, h1, acc[i][1]);
            old.x -= wgt * l0; old.y -= wgt * h0; old.z -= wgt * l1; old.w -= wgt * h1;
            *reinterpret_cast<float4*>(Wp) = old;
        }
    } else if (f < 100352) {
        // W1[k,j] -= w * sum_m K[m,k] * dh[m,j]
        int g = f - 50176;
        int j0 = (g % 128) * 4;
        int dd0 = (g / 128) * 8;
        ull acc[8][2];
#pragma unroll
        for (int i = 0; i < 8; i++) { acc[i][0] = 0ULL; acc[i][1] = 0ULL; }
#pragma unroll 4
        for (int m = 0; m < CHUNK; m++) {
            ulonglong2 gg = *reinterpret_cast<const ulonglong2*>(g_dh + m * DH + j0);
            const float* Km = Kc + m * DM + dd0;
#pragma unroll
            for (int i = 0; i < 8; i++) {
                ull k2 = pk2(Km[i], Km[i]);
                FFMA2(acc[i][0], k2, gg.x);
                FFMA2(acc[i][1], k2, gg.y);
            }
        }
#pragma unroll
        for (int i = 0; i < 8; i++) {
            float* Wp = g_W1 + (dd0 + i) * DH + j0;
            float4 old = *reinterpret_cast<float4*>(Wp);
            float l0, h0, l1, h1;
            upk2(l0, h0, acc[i][0]); upk2(l1, h1, acc[i][1]);
            old.x -= wgt * l0; old.y -= wgt * h0; old.z -= wgt * l1; old.w -= wgt * h1;
            *reinterpret_cast<float4*>(Wp) = old;
        }
    } else if (f < 104000) {
        int i = f - 100352;
        if (i < DH) {
            float s = 0.f;
#pragma unroll 8
            for (int m = 0; m < CHUNK; m++) s += g_dh[m * DH + i];
            g_b1[i] -= wgt * s;
        } else if (i < DH + DM) {
            int d = i - DH;
            float s = 0.f;
#pragma unroll 8
            for (int m = 0; m < CHUNK; m++) s += g_dpred[m * DM + d];
            g_b2[d] -= wgt * s;
        }
    } else if (f < 136768) {
        // A2[m,j] = gelu(H[m,j] - w*(sum_mp G[m,mp]*dh[mp,j] + sum_mp dh[mp,j]))
        int e = f - 104000;
        int m = e >> 9;
        int j = e & (DH - 1);
        float s = 0.f, cs = 0.f;
        const float* Gm = g_G + m * CHUNK;
#pragma unroll 8
        for (int mp = 0; mp < CHUNK; mp++) {
            float d = g_dh[mp * DH + j];
            s += Gm[mp] * d;
            cs += d;
        }
        float H2 = g_H[e] - wgt * (s + cs);
        g_A2[e] = gelu_f(H2);
    }
}

// ---------------- launch ----------------
extern "C" void kernel_launch(void* const* d_in, const int* in_sizes, int n_in,
                              void* d_out, int out_size) {
    const float* x   = (const float*)d_in[0];
    const float* ckw = (const float*)d_in[1];
    const float* ckb = (const float*)d_in[2];
    const float* cvw = (const float*)d_in[3];
    const float* cvb = (const float*)d_in[4];
    const float* rsk = (const float*)d_in[5];
    const float* rsv = (const float*)d_in[6];
    const float* W1  = (const float*)d_in[7];
    const float* b1  = (const float*)d_in[8];
    const float* W2  = (const float*)d_in[9];
    const float* b2  = (const float*)d_in[10];
    float* out = (float*)d_out;

    // weights[i] = eta0*alpha^i * alpha^(CHUNK-1)/alpha^i = const
    float wgt = (float)(0.1 * pow(0.9, 63.0));

    float* nk_base;  cudaGetSymbolAddress((void**)&nk_base, g_nk);
    float* a_base;   cudaGetSymbolAddress((void**)&a_base, g_A);
    float* a2_base;  cudaGetSymbolAddress((void**)&a2_base, g_A2);

    prologue_kernel<<<2080, 256>>>(x, ckw, ckb, cvw, cvb, rsk, rsv, W1, b1, W2, b2);

    for (int c = 0; c < NCHUNK; c++) {
        const float* Kc_p = nk_base + c * (CHUNK * DM);
        fwd_kgram_kernel<<<324, 256>>>(Kc_p);
        reduce1G_kernel<<<36, 256>>>();
        pred_gemm_kernel<<<196, 256>>>(a_base);
        reduce2_kernel<<<196, 256>>>(c, 0, out);
        dadh_gemm_kernel<<<196, 256>>>();
        reduceDh_kernel<<<32, 256>>>();
        update_recall_kernel<<<535, 256>>>(Kc_p, wgt);
        pred_gemm_kernel<<<196, 256>>>(a2_base);
        reduce2_kernel<<<196, 256>>>(c, 1, out);
    }
}

// round 9
// speedup vs baseline: 1.0310x; 1.0310x over previous
#include <cuda_runtime.h>
#include <math.h>

#define T_TOK 512
#define CHUNK 64
#define NCHUNK 8
#define HH 28
#define WW 28
#define CC 4
#define DM 3136
#define DH 512

#define FSEG 98    // fwd/dadh split-K segments (k = 32 each)
#define PSEG 16    // pred split-K segments (k = 32 each)
#define GSEG 8     // kgram split-K segments (k = 392 each)

typedef unsigned long long ull;

// ---------------- f32x2 helpers ----------------
__device__ __forceinline__ ull pk2(float lo, float hi) {
    ull r; asm("mov.b64 %0, {%1,%2};" : "=l"(r) : "f"(lo), "f"(hi)); return r;
}
__device__ __forceinline__ void upk2(float& lo, float& hi, ull v) {
    asm("mov.b64 {%0,%1}, %2;" : "=f"(lo), "=f"(hi) : "l"(v));
}
#define FFMA2(d, a, b) asm("fma.rn.f32x2 %0, %1, %2, %0;" : "+l"(d) : "l"(a), "l"(b))

// ---------------- device scratch ----------------
__device__ __align__(16) float g_nk[T_TOK * DM];
__device__ __align__(16) float g_nv[T_TOK * DM];
__device__ __align__(16) float g_W1[DM * DH];
__device__ __align__(16) float g_W2[DH * DM];
__device__ __align__(16) float g_b1[DH];
__device__ __align__(16) float g_b2[DM];
__device__ __align__(16) float g_H[CHUNK * DH];
__device__ __align__(16) float g_A[CHUNK * DH];
__device__ __align__(16) float g_A2[CHUNK * DH];
__device__ __align__(16) float g_dpred[CHUNK * DM];
__device__ __align__(16) float g_dh[CHUNK * DH];
__device__ __align__(16) float g_G[CHUNK * CHUNK];
__device__ __align__(16) float g_fpart[FSEG * CHUNK * DH];    // 12.8 MB (fwd & dadh partials)
__device__ __align__(16) float g_ppart[PSEG * CHUNK * DM];    // 12.8 MB (pred partials)
__device__ __align__(16) float g_gpart[GSEG * CHUNK * CHUNK];

// ---------------- math helpers ----------------
__device__ __forceinline__ float gelu_f(float x) {
    const float c = 0.7978845608028654f, a = 0.044715f;
    float u = c * (x + a * x * x * x);
    return 0.5f * x * (1.0f + tanhf(u));
}
__device__ __forceinline__ float dgelu_f(float x) {
    const float c = 0.7978845608028654f, a = 0.044715f;
    float x2 = x * x;
    float u = c * (x + a * x * x2);
    float th = tanhf(u);
    return 0.5f * (1.0f + th) + 0.5f * x * (1.0f - th * th) * c * (1.0f + 3.0f * a * x2);
}

// ---------------- prologue: conv3x3+rmsnorm and param copy ----------------
__global__ void prologue_kernel(const float* __restrict__ x,
                                const float* __restrict__ wk, const float* __restrict__ bk,
                                const float* __restrict__ wv, const float* __restrict__ bv,
                                const float* __restrict__ sk, const float* __restrict__ sv,
                                const float* __restrict__ W1, const float* __restrict__ b1,
                                const float* __restrict__ W2, const float* __restrict__ b2) {
    int tid = threadIdx.x;
    if (blockIdx.x < 1568) {
        __shared__ float swk[144], swv[144], sbk[4], sbv[4], ssk[4], ssv[4];
        if (tid < 144) { swk[tid] = wk[tid]; swv[tid] = wv[tid]; }
        if (tid < 4) { sbk[tid] = bk[tid]; sbv[tid] = bv[tid]; ssk[tid] = sk[tid]; ssv[tid] = sv[tid]; }
        __syncthreads();
        int idx = blockIdx.x * 256 + tid;   // 401408 exact
        int w = idx % WW;
        int h = (idx / WW) % HH;
        int t = idx / (HH * WW);
        float acck[4], accv[4];
#pragma unroll
        for (int o = 0; o < 4; o++) { acck[o] = sbk[o]; accv[o] = sbv[o]; }
        const float* xt = x + t * (CC * HH * WW);
#pragma unroll
        for (int kh = 0; kh < 3; kh++) {
            int hy = h + kh - 1;
            if (hy < 0 || hy >= HH) continue;
#pragma unroll
            for (int kw = 0; kw < 3; kw++) {
                int wx = w + kw - 1;
                if (wx < 0 || wx >= WW) continue;
                int wbase = (kh * 3 + kw) * 16;
#pragma unroll
                for (int ci = 0; ci < 4; ci++) {
                    float xv = xt[ci * (HH * WW) + hy * WW + wx];
#pragma unroll
                    for (int o = 0; o < 4; o++) {
                        acck[o] += xv * swk[wbase + ci * 4 + o];
                        accv[o] += xv * swv[wbase + ci * 4 + o];
                    }
                }
            }
        }
        float msk = 0.f, msv = 0.f;
#pragma unroll
        for (int o = 0; o < 4; o++) { msk += acck[o] * acck[o]; msv += accv[o] * accv[o]; }
        float ik = rsqrtf(msk * 0.25f + 1e-6f);
        float iv = rsqrtf(msv * 0.25f + 1e-6f);
        int base = t * DM + (h * WW + w) * CC;
#pragma unroll
        for (int o = 0; o < 4; o++) {
            g_nk[base + o] = acck[o] * ik * ssk[o];
            g_nv[base + o] = accv[o] * iv * ssv[o];
        }
    } else {
        int i = (blockIdx.x - 1568) * 256 + tid;   // 131072 threads
        for (int k = i; k < DM * DH; k += 131072) { g_W1[k] = W1[k]; g_W2[k] = W2[k]; }
        if (i < DH) g_b1[i] = b1[i];
        if (i < DM) g_b2[i] = b2[i];
    }
}

// ---------------- fwd split-K GEMM + kgram ----------------
// blocks [0,392): fpart[seg][m][n] = sum_{k in seg32} K[m,k]*W1[k,n]  (4m x 8n, f32x2)
// blocks [392,520): gpart[seg][m][n] = sum_{k in seg392} K[m,k]*K[n,k]
__global__ void __launch_bounds__(256) fwd_kgram_kernel(const float* __restrict__ Kc) {
    if (blockIdx.x < 392) {
        int f = blockIdx.x * 256 + threadIdx.x;   // 100352
        int n0 = (f & 63) * 8;
        int m0 = ((f >> 6) & 15) * 4;
        int seg = f >> 10;                 // 0..97
        int k0 = seg * 32;
        const float* K = Kc + m0 * DM;
        const float* Wp = g_W1 + n0;
        ull acc[4][4];
#pragma unroll
        for (int i = 0; i < 4; i++)
#pragma unroll
            for (int j = 0; j < 4; j++) acc[i][j] = 0ULL;
#pragma unroll 8
        for (int k = k0; k < k0 + 32; k++) {
            ulonglong2 wa = *reinterpret_cast<const ulonglong2*>(Wp + (size_t)k * DH);
            ulonglong2 wb = *reinterpret_cast<const ulonglong2*>(Wp + (size_t)k * DH + 4);
            ull bv[4] = {wa.x, wa.y, wb.x, wb.y};
            float x0 = K[k], x1 = K[DM + k], x2 = K[2 * DM + k], x3 = K[3 * DM + k];
            ull av[4] = {pk2(x0, x0), pk2(x1, x1), pk2(x2, x2), pk2(x3, x3)};
#pragma unroll
            for (int i = 0; i < 4; i++)
#pragma unroll
                for (int j = 0; j < 4; j++) FFMA2(acc[i][j], av[i], bv[j]);
        }
        float* P = g_fpart + seg * (CHUNK * DH) + m0 * DH + n0;
#pragma unroll
        for (int i = 0; i < 4; i++) {
            float o0, o1, o2, o3, o4, o5, o6, o7;
            upk2(o0, o1, acc[i][0]); upk2(o2, o3, acc[i][1]);
            upk2(o4, o5, acc[i][2]); upk2(o6, o7, acc[i][3]);
            *reinterpret_cast<float4*>(P + i * DH)     = make_float4(o0, o1, o2, o3);
            *reinterpret_cast<float4*>(P + i * DH + 4) = make_float4(o4, o5, o6, o7);
        }
    } else {
        // kgram: gpart[seg][m][n] = sum over 392 k of K[m,k]*K[n,k]
        int t = (blockIdx.x - 392) * 256 + threadIdx.x;   // 32768
        int seg = t >> 12;                 // 0..7
        int o = t & 4095;
        int m = o >> 6;
        int n = o & 63;
        int kbase = seg * 392;
        const ull* pa = reinterpret_cast<const ull*>(Kc + m * DM + kbase);
        const ull* pb = reinterpret_cast<const ull*>(Kc + n * DM + kbase);
        ull acc2 = 0ULL;
#pragma unroll 8
        for (int k2 = 0; k2 < 196; k2++) FFMA2(acc2, pa[k2], pb[k2]);
        float lo, hi;
        upk2(lo, hi, acc2);
        g_gpart[seg * 4096 + o] = lo + hi;
    }
}

// ---------------- reduce fwd partials -> H, A (4-way sliced) ; and G ----------------
// blocks [0,512): H/A — block handles 64 outputs, 4 slices of ~25 segs each
// blocks [512,528): G — scalar, 8 deep
__global__ void __launch_bounds__(256) reduce1G_kernel() {
    if (blockIdx.x < 512) {
        __shared__ float red[256];
        int tid = threadIdx.x;
        int slice = tid >> 6;              // 0..3
        int o = tid & 63;
        int idx = blockIdx.x * 64 + o;     // 0..32767
        const int start[4] = {0, 25, 50, 74};
        const int cnt[4] = {25, 25, 24, 24};
        float s = 0.f;
        int s0 = start[slice], n = cnt[slice];
        const float* P = g_fpart + idx;
#pragma unroll 5
        for (int sg = 0; sg < n; sg++)
            s += P[(s0 + sg) * (CHUNK * DH)];
        red[tid] = s;
        __syncthreads();
        if (slice == 0) {
            float t = red[o] + red[64 + o] + red[128 + o] + red[192 + o] + g_b1[idx & (DH - 1)];
            g_H[idx] = t;
            g_A[idx] = gelu_f(t);
        }
    } else {
        int t = (blockIdx.x - 512) * 256 + threadIdx.x;   // 4096
        float s = 0.f;
#pragma unroll
        for (int sg = 0; sg < GSEG; sg++) s += g_gpart[sg * 4096 + t];
        g_G[t] = s;
    }
}

// ---------------- pred split-K GEMM: ppart[seg][m][d] = sum_{j in seg32} A[m,j]*W2[j,d] ----------------
__global__ void __launch_bounds__(256) pred_gemm_kernel(const float* __restrict__ Asrc) {
    int f = blockIdx.x * 256 + threadIdx.x;    // 392 blocks = 100352
    int d0 = (f % 392) * 8;
    int m0 = ((f / 392) & 15) * 4;
    int seg = f / 6272;                        // 0..15
    int j0 = seg * 32;
    const float* A0 = Asrc + m0 * DH;
    const float* Wp = g_W2 + d0;
    ull acc[4][4];
#pragma unroll
    for (int i = 0; i < 4; i++)
#pragma unroll
        for (int j = 0; j < 4; j++) acc[i][j] = 0ULL;
#pragma unroll 8
    for (int j = j0; j < j0 + 32; j++) {
        ulonglong2 wa = *reinterpret_cast<const ulonglong2*>(Wp + (size_t)j * DM);
        ulonglong2 wb = *reinterpret_cast<const ulonglong2*>(Wp + (size_t)j * DM + 4);
        ull bv[4] = {wa.x, wa.y, wb.x, wb.y};
        float a0 = A0[j], a1 = A0[DH + j], a2 = A0[2 * DH + j], a3 = A0[3 * DH + j];
        ull av[4] = {pk2(a0, a0), pk2(a1, a1), pk2(a2, a2), pk2(a3, a3)};
#pragma unroll
        for (int i = 0; i < 4; i++)
#pragma unroll
            for (int jj = 0; jj < 4; jj++) FFMA2(acc[i][jj], av[i], bv[jj]);
    }
    float* P = g_ppart + seg * (CHUNK * DM) + m0 * DM + d0;
#pragma unroll
    for (int i = 0; i < 4; i++) {
        float o0, o1, o2, o3, o4, o5, o6, o7;
        upk2(o0, o1, acc[i][0]); upk2(o2, o3, acc[i][1]);
        upk2(o4, o5, acc[i][2]); upk2(o6, o7, acc[i][3]);
        *reinterpret_cast<float4*>(P + i * DM)     = make_float4(o0, o1, o2, o3);
        *reinterpret_cast<float4*>(P + i * DM + 4) = make_float4(o4, o5, o6, o7);
    }
}

// ---------------- reduce pred partials: mode0 -> dpred, mode1 -> out ----------------
__global__ void reduce2_kernel(int c, int mode, float* __restrict__ out) {
    int idx = blockIdx.x * 256 + threadIdx.x;   // 784 blocks = 200704 exact
    int d = idx % DM;
    float s = g_b2[d];
#pragma unroll
    for (int sg = 0; sg < PSEG; sg++) s += g_ppart[sg * (CHUNK * DM) + idx];
    if (mode == 0)
        g_dpred[idx] = 2.0f * (s - g_nv[c * (CHUNK * DM) + idx]);
    else
        out[c * (CHUNK * DM) + idx] = s;
}

// ---------------- dadh split-K GEMM: fpart[seg][m][j] = sum_{d in seg32} dpred[m,d]*W2[j,d] ----------------
__global__ void __launch_bounds__(256) dadh_gemm_kernel() {
    int f = blockIdx.x * 256 + threadIdx.x;    // 392 blocks = 100352
    int n0 = (f & 63) * 8;                     // j tile
    int m0 = ((f >> 6) & 15) * 4;
    int seg = f >> 10;                         // 0..97
    int k0 = seg * 32;
    const float* A0 = g_dpred + m0 * DM + k0;
    const float* B0 = g_W2 + n0 * DM + k0;
    ull acc[4][8];
#pragma unroll
    for (int i = 0; i < 4; i++)
#pragma unroll
        for (int j = 0; j < 8; j++) acc[i][j] = 0ULL;
#pragma unroll 2
    for (int k4 = 0; k4 < 8; k4++) {
        ulonglong2 a[4];
#pragma unroll
        for (int i = 0; i < 4; i++)
            a[i] = *reinterpret_cast<const ulonglong2*>(A0 + i * DM + k4 * 4);
#pragma unroll
        for (int j = 0; j < 8; j++) {
            ulonglong2 b = *reinterpret_cast<const ulonglong2*>(B0 + j * DM + k4 * 4);
#pragma unroll
            for (int i = 0; i < 4; i++) {
                FFMA2(acc[i][j], a[i].x, b.x);
                FFMA2(acc[i][j], a[i].y, b.y);
            }
        }
    }
    float* P = g_fpart + seg * (CHUNK * DH) + m0 * DH + n0;
#pragma unroll
    for (int i = 0; i < 4; i++) {
        float o[8];
#pragma unroll
        for (int j = 0; j < 8; j++) {
            float lo, hi; upk2(lo, hi, acc[i][j]);
            o[j] = lo + hi;
        }
        *reinterpret_cast<float4*>(P + i * DH)     = make_float4(o[0], o[1], o[2], o[3]);
        *reinterpret_cast<float4*>(P + i * DH + 4) = make_float4(o[4], o[5], o[6], o[7]);
    }
}

// ---------------- reduce dadh partials -> dh (4-way sliced, with dgelu) ----------------
__global__ void __launch_bounds__(256) reduceDh_kernel() {
    __shared__ float red[256];
    int tid = threadIdx.x;
    int slice = tid >> 6;
    int o = tid & 63;
    int idx = blockIdx.x * 64 + o;     // 512 blocks -> 32768 outputs
    const int start[4] = {0, 25, 50, 74};
    const int cnt[4] = {25, 25, 24, 24};
    float s = 0.f;
    int s0 = start[slice], n = cnt[slice];
    const float* P = g_fpart + idx;
#pragma unroll 5
    for (int sg = 0; sg < n; sg++)
        s += P[(s0 + sg) * (CHUNK * DH)];
    red[tid] = s;
    __syncthreads();
    if (slice == 0) {
        float t = red[o] + red[64 + o] + red[128 + o] + red[192 + o];
        g_dh[idx] = t * dgelu_f(g_H[idx]);
    }
}

// ---------------- fused: W2/W1/bias updates + recall activation A2 (via Gram) ----------------
// [0,100352):        W2[j,d] -= w * sum_m A[m,j]*dpred[m,d]      (4j x 4d tiles)
// [100352,200704):   W1[k,j] -= w * sum_m K[m,k]*dh[m,j]         (4k x 4j tiles)
// [200704,204352):   biases
// [204352,237120):   A2 = gelu(H - w*(G@dh + colsum(dh)))
__global__ void __launch_bounds__(256) update_recall_kernel(const float* __restrict__ Kc, float wgt) {
    int f = blockIdx.x * 256 + threadIdx.x;
    if (f < 100352) {
        int d0 = (f % 784) * 4;
        int j0 = (f / 784) * 4;
        ull acc[4][2];
#pragma unroll
        for (int i = 0; i < 4; i++) { acc[i][0] = 0ULL; acc[i][1] = 0ULL; }
#pragma unroll 4
        for (int m = 0; m < CHUNK; m++) {
            ulonglong2 p = *reinterpret_cast<const ulonglong2*>(g_dpred + m * DM + d0);
            const float* Am = g_A + m * DH + j0;
#pragma unroll
            for (int i = 0; i < 4; i++) {
                ull a2 = pk2(Am[i], Am[i]);
                FFMA2(acc[i][0], a2, p.x);
                FFMA2(acc[i][1], a2, p.y);
            }
        }
#pragma unroll
        for (int i = 0; i < 4; i++) {
            float* Wp = g_W2 + (j0 + i) * DM + d0;
            float4 old = *reinterpret_cast<float4*>(Wp);
            float l0, h0, l1, h1;
            upk2(l0, h0, acc[i][0]); upk2(l1, h1, acc[i][1]);
            old.x -= wgt * l0; old.y -= wgt * h0; old.z -= wgt * l1; old.w -= wgt * h1;
            *reinterpret_cast<float4*>(Wp) = old;
        }
    } else if (f < 200704) {
        int g = f - 100352;
        int j0 = (g % 128) * 4;
        int kk0 = (g / 128) * 4;
        ull acc[4][2];
#pragma unroll
        for (int i = 0; i < 4; i++) { acc[i][0] = 0ULL; acc[i][1] = 0ULL; }
#pragma unroll 4
        for (int m = 0; m < CHUNK; m++) {
            ulonglong2 gg = *reinterpret_cast<const ulonglong2*>(g_dh + m * DH + j0);
            const float* Km = Kc + m * DM + kk0;
#pragma unroll
            for (int i = 0; i < 4; i++) {
                ull k2 = pk2(Km[i], Km[i]);
                FFMA2(acc[i][0], k2, gg.x);
                FFMA2(acc[i][1], k2, gg.y);
            }
        }
#pragma unroll
        for (int i = 0; i < 4; i++) {
            float* Wp = g_W1 + (kk0 + i) * DH + j0;
            float4 old = *reinterpret_cast<float4*>(Wp);
            float l0, h0, l1, h1;
            upk2(l0, h0, acc[i][0]); upk2(l1, h1, acc[i][1]);
            old.x -= wgt * l0; old.y -= wgt * h0; old.z -= wgt * l1; old.w -= wgt * h1;
            *reinterpret_cast<float4*>(Wp) = old;
        }
    } else if (f < 204352) {
        int i = f - 200704;
        if (i < DH) {
            float s = 0.f;
#pragma unroll 8
            for (int m = 0; m < CHUNK; m++) s += g_dh[m * DH + i];
            g_b1[i] -= wgt * s;
        } else if (i < DH + DM) {
            int d = i - DH;
            float s = 0.f;
#pragma unroll 8
            for (int m = 0; m < CHUNK; m++) s += g_dpred[m * DM + d];
            g_b2[d] -= wgt * s;
        }
    } else if (f < 237120) {
        int e = f - 204352;
        int m = e >> 9;
        int j = e & (DH - 1);
        float s = 0.f, cs = 0.f;
        const float* Gm = g_G + m * CHUNK;
#pragma unroll 8
        for (int mp = 0; mp < CHUNK; mp++) {
            float d = g_dh[mp * DH + j];
            s += Gm[mp] * d;
            cs += d;
        }
        float H2 = g_H[e] - wgt * (s + cs);
        g_A2[e] = gelu_f(H2);
    }
}

// ---------------- launch ----------------
extern "C" void kernel_launch(void* const* d_in, const int* in_sizes, int n_in,
                              void* d_out, int out_size) {
    const float* x   = (const float*)d_in[0];
    const float* ckw = (const float*)d_in[1];
    const float* ckb = (const float*)d_in[2];
    const float* cvw = (const float*)d_in[3];
    const float* cvb = (const float*)d_in[4];
    const float* rsk = (const float*)d_in[5];
    const float* rsv = (const float*)d_in[6];
    const float* W1  = (const float*)d_in[7];
    const float* b1  = (const float*)d_in[8];
    const float* W2  = (const float*)d_in[9];
    const float* b2  = (const float*)d_in[10];
    float* out = (float*)d_out;

    // weights[i] = eta0*alpha^i * alpha^(CHUNK-1)/alpha^i = const
    float wgt = (float)(0.1 * pow(0.9, 63.0));

    float* nk_base;  cudaGetSymbolAddress((void**)&nk_base, g_nk);
    float* a_base;   cudaGetSymbolAddress((void**)&a_base, g_A);
    float* a2_base;  cudaGetSymbolAddress((void**)&a2_base, g_A2);

    prologue_kernel<<<2080, 256>>>(x, ckw, ckb, cvw, cvb, rsk, rsv, W1, b1, W2, b2);

    for (int c = 0; c < NCHUNK; c++) {
        const float* Kc_p = nk_base + c * (CHUNK * DM);
        fwd_kgram_kernel<<<520, 256>>>(Kc_p);
        reduce1G_kernel<<<528, 256>>>();
        pred_gemm_kernel<<<392, 256>>>(a_base);
        reduce2_kernel<<<784, 256>>>(c, 0, out);
        dadh_gemm_kernel<<<392, 256>>>();
        reduceDh_kernel<<<512, 256>>>();
        update_recall_kernel<<<927, 256>>>(Kc_p, wgt);
        pred_gemm_kernel<<<392, 256>>>(a2_base);
        reduce2_kernel<<<784, 256>>>(c, 1, out);
    }
}

// round 10
// speedup vs baseline: 1.7277x; 1.6758x over previous
#include <cuda_runtime.h>
#include <math.h>

#define T_TOK 512
#define CHUNK 64
#define NCHUNK 8
#define HH 28
#define WW 28
#define CC 4
#define DM 3136
#define DH 512

#define FSEG 98    // fwd/dadh split-K segments (k = 32 each)
#define PSEG 16    // pred split-K segments (k = 32 each)
#define GSEG 8     // kgram split-K segments (k = 392 each)

typedef unsigned long long ull;

// ---------------- f32x2 helpers ----------------
__device__ __forceinline__ ull pk2(float lo, float hi) {
    ull r; asm("mov.b64 %0, {%1,%2};" : "=l"(r) : "f"(lo), "f"(hi)); return r;
}
__device__ __forceinline__ void upk2(float& lo, float& hi, ull v) {
    asm("mov.b64 {%0,%1}, %2;" : "=f"(lo), "=f"(hi) : "l"(v));
}
#define FFMA2(d, a, b) asm("fma.rn.f32x2 %0, %1, %2, %0;" : "+l"(d) : "l"(a), "l"(b))

// ---------------- device scratch ----------------
__device__ __align__(16) float g_nk[T_TOK * DM];
__device__ __align__(16) float g_nv[T_TOK * DM];
__device__ __align__(16) float g_W1[DM * DH];
__device__ __align__(16) float g_W2[DH * DM];
__device__ __align__(16) float g_b1[DH];
__device__ __align__(16) float g_b2[DM];
__device__ __align__(16) float g_H[CHUNK * DH];
__device__ __align__(16) float g_A[CHUNK * DH];
__device__ __align__(16) float g_A2[CHUNK * DH];
__device__ __align__(16) float g_dpred[CHUNK * DM];
__device__ __align__(16) float g_dh[CHUNK * DH];
__device__ __align__(16) float g_G[CHUNK * CHUNK];
__device__ __align__(16) float g_fpart[FSEG * CHUNK * DH];    // 12.8 MB (fwd & dadh partials)
__device__ __align__(16) float g_ppart[PSEG * CHUNK * DM];    // 12.8 MB (pred partials)
__device__ __align__(16) float g_gpart[GSEG * CHUNK * CHUNK];

// ---------------- math helpers ----------------
__device__ __forceinline__ float gelu_f(float x) {
    const float c = 0.7978845608028654f, a = 0.044715f;
    float u = c * (x + a * x * x * x);
    return 0.5f * x * (1.0f + tanhf(u));
}
__device__ __forceinline__ float dgelu_f(float x) {
    const float c = 0.7978845608028654f, a = 0.044715f;
    float x2 = x * x;
    float u = c * (x + a * x * x2);
    float th = tanhf(u);
    return 0.5f * (1.0f + th) + 0.5f * x * (1.0f - th * th) * c * (1.0f + 3.0f * a * x2);
}

// ---------------- prologue: conv3x3+rmsnorm and param copy ----------------
__global__ void prologue_kernel(const float* __restrict__ x,
                                const float* __restrict__ wk, const float* __restrict__ bk,
                                const float* __restrict__ wv, const float* __restrict__ bv,
                                const float* __restrict__ sk, const float* __restrict__ sv,
                                const float* __restrict__ W1, const float* __restrict__ b1,
                                const float* __restrict__ W2, const float* __restrict__ b2) {
    int tid = threadIdx.x;
    if (blockIdx.x < 1568) {
        __shared__ float swk[144], swv[144], sbk[4], sbv[4], ssk[4], ssv[4];
        if (tid < 144) { swk[tid] = wk[tid]; swv[tid] = wv[tid]; }
        if (tid < 4) { sbk[tid] = bk[tid]; sbv[tid] = bv[tid]; ssk[tid] = sk[tid]; ssv[tid] = sv[tid]; }
        __syncthreads();
        int idx = blockIdx.x * 256 + tid;   // 401408 exact
        int w = idx % WW;
        int h = (idx / WW) % HH;
        int t = idx / (HH * WW);
        float acck[4], accv[4];
#pragma unroll
        for (int o = 0; o < 4; o++) { acck[o] = sbk[o]; accv[o] = sbv[o]; }
        const float* xt = x + t * (CC * HH * WW);
#pragma unroll
        for (int kh = 0; kh < 3; kh++) {
            int hy = h + kh - 1;
            if (hy < 0 || hy >= HH) continue;
#pragma unroll
            for (int kw = 0; kw < 3; kw++) {
                int wx = w + kw - 1;
                if (wx < 0 || wx >= WW) continue;
                int wbase = (kh * 3 + kw) * 16;
#pragma unroll
                for (int ci = 0; ci < 4; ci++) {
                    float xv = xt[ci * (HH * WW) + hy * WW + wx];
#pragma unroll
                    for (int o = 0; o < 4; o++) {
                        acck[o] += xv * swk[wbase + ci * 4 + o];
                        accv[o] += xv * swv[wbase + ci * 4 + o];
                    }
                }
            }
        }
        float msk = 0.f, msv = 0.f;
#pragma unroll
        for (int o = 0; o < 4; o++) { msk += acck[o] * acck[o]; msv += accv[o] * accv[o]; }
        float ik = rsqrtf(msk * 0.25f + 1e-6f);
        float iv = rsqrtf(msv * 0.25f + 1e-6f);
        int base = t * DM + (h * WW + w) * CC;
#pragma unroll
        for (int o = 0; o < 4; o++) {
            g_nk[base + o] = acck[o] * ik * ssk[o];
            g_nv[base + o] = accv[o] * iv * ssv[o];
        }
    } else {
        int i = (blockIdx.x - 1568) * 256 + tid;   // 131072 threads
        for (int k = i; k < DM * DH; k += 131072) { g_W1[k] = W1[k]; g_W2[k] = W2[k]; }
        if (i < DH) g_b1[i] = b1[i];
        if (i < DM) g_b2[i] = b2[i];
    }
}

// ---------------- unified smem-tiled split-K GEMM (784 main blocks) ----------------
// blocks [0,784): Cpart[seg][m 0..63][n0g..n0g+64] = sum_{k in seg32} A[m,k]*B(k,n)
//   where B(k,n) = B[k*ldb+n] (transb=0) or B[n*ldb+k] (transb=1)
// blocks [784,912) (only when kgram=1): gpart[gseg][m][n] = sum_{k in gseg392} A[m,k]*A[n,k]
__global__ void __launch_bounds__(256) tile_gemm_kernel(
    const float* __restrict__ A, const float* __restrict__ B, float* __restrict__ C,
    int ntiles, int lda, int ldb, int ntot, int transb, int kgram)
{
    if (blockIdx.x < 784) {
        __shared__ float sA[32][68];
        __shared__ float sB[32][68];
        int tid = threadIdx.x;
        int nt = blockIdx.x % ntiles;
        int seg = blockIdx.x / ntiles;
        int n0g = nt * 64;
        int k0 = seg * 32;

        // load A (64m x 32k) transposed -> sA[k][m]
        for (int i = tid; i < 512; i += 256) {
            int m = i >> 3;
            int f4 = (i & 7) * 4;
            float4 v = *reinterpret_cast<const float4*>(A + (size_t)m * lda + k0 + f4);
            sA[f4][m] = v.x; sA[f4 + 1][m] = v.y; sA[f4 + 2][m] = v.z; sA[f4 + 3][m] = v.w;
        }
        // load B tile -> sB[k][n]
        if (!transb) {
            for (int i = tid; i < 512; i += 256) {
                int k = i >> 4;
                int n4 = (i & 15) * 4;
                float4 v = *reinterpret_cast<const float4*>(B + (size_t)(k0 + k) * ldb + n0g + n4);
                *reinterpret_cast<float4*>(&sB[k][n4]) = v;
            }
        } else {
            for (int i = tid; i < 512; i += 256) {
                int n = i >> 3;
                int f4 = (i & 7) * 4;
                float4 v = *reinterpret_cast<const float4*>(B + (size_t)(n0g + n) * ldb + k0 + f4);
                sB[f4][n] = v.x; sB[f4 + 1][n] = v.y; sB[f4 + 2][n] = v.z; sB[f4 + 3][n] = v.w;
            }
        }
        __syncthreads();

        int m0 = (tid >> 4) * 4;
        int n0 = (tid & 15) * 4;
        ull acc[4][2];
#pragma unroll
        for (int i = 0; i < 4; i++) { acc[i][0] = 0ULL; acc[i][1] = 0ULL; }
#pragma unroll
        for (int kk = 0; kk < 32; kk++) {
            float4 a = *reinterpret_cast<const float4*>(&sA[kk][m0]);
            ulonglong2 b = *reinterpret_cast<const ulonglong2*>(&sB[kk][n0]);
            ull a0 = pk2(a.x, a.x), a1 = pk2(a.y, a.y), a2 = pk2(a.z, a.z), a3 = pk2(a.w, a.w);
            FFMA2(acc[0][0], a0, b.x); FFMA2(acc[0][1], a0, b.y);
            FFMA2(acc[1][0], a1, b.x); FFMA2(acc[1][1], a1, b.y);
            FFMA2(acc[2][0], a2, b.x); FFMA2(acc[2][1], a2, b.y);
            FFMA2(acc[3][0], a3, b.x); FFMA2(acc[3][1], a3, b.y);
        }
        float* P = C + (size_t)seg * (64 * (size_t)ntot) + (size_t)m0 * ntot + n0g + n0;
#pragma unroll
        for (int i = 0; i < 4; i++) {
            float l0, h0, l1, h1;
            upk2(l0, h0, acc[i][0]); upk2(l1, h1, acc[i][1]);
            *reinterpret_cast<float4*>(P + (size_t)i * ntot) = make_float4(l0, h0, l1, h1);
        }
    } else if (kgram) {
        // gpart[gseg][m][n] = sum over 392 k of A[m,k]*A[n,k]
        int t = (blockIdx.x - 784) * 256 + threadIdx.x;   // 32768
        int gseg = t >> 12;                // 0..7
        int o = t & 4095;
        int m = o >> 6;
        int n = o & 63;
        int kbase = gseg * 392;
        const ull* pa = reinterpret_cast<const ull*>(A + (size_t)m * DM + kbase);
        const ull* pb = reinterpret_cast<const ull*>(A + (size_t)n * DM + kbase);
        ull acc2 = 0ULL;
#pragma unroll 8
        for (int k2 = 0; k2 < 196; k2++) FFMA2(acc2, pa[k2], pb[k2]);
        float lo, hi;
        upk2(lo, hi, acc2);
        g_gpart[gseg * 4096 + o] = lo + hi;
    }
}

// ---------------- reduce fwd partials -> H, A (4-way sliced) ; and G ----------------
__global__ void __launch_bounds__(256) reduce1G_kernel() {
    if (blockIdx.x < 512) {
        __shared__ float red[256];
        int tid = threadIdx.x;
        int slice = tid >> 6;              // 0..3
        int o = tid & 63;
        int idx = blockIdx.x * 64 + o;     // 0..32767
        const int start[4] = {0, 25, 50, 74};
        const int cnt[4] = {25, 25, 24, 24};
        float s = 0.f;
        int s0 = start[slice], n = cnt[slice];
        const float* P = g_fpart + idx;
#pragma unroll 5
        for (int sg = 0; sg < n; sg++)
            s += P[(s0 + sg) * (CHUNK * DH)];
        red[tid] = s;
        __syncthreads();
        if (slice == 0) {
            float t = red[o] + red[64 + o] + red[128 + o] + red[192 + o] + g_b1[idx & (DH - 1)];
            g_H[idx] = t;
            g_A[idx] = gelu_f(t);
        }
    } else {
        int t = (blockIdx.x - 512) * 256 + threadIdx.x;   // 4096
        float s = 0.f;
#pragma unroll
        for (int sg = 0; sg < GSEG; sg++) s += g_gpart[sg * 4096 + t];
        g_G[t] = s;
    }
}

// ---------------- reduce pred partials: mode0 -> dpred, mode1 -> out ----------------
__global__ void reduce2_kernel(int c, int mode, float* __restrict__ out) {
    int idx = blockIdx.x * 256 + threadIdx.x;   // 784 blocks = 200704 exact
    int d = idx % DM;
    float s = g_b2[d];
#pragma unroll
    for (int sg = 0; sg < PSEG; sg++) s += g_ppart[sg * (CHUNK * DM) + idx];
    if (mode == 0)
        g_dpred[idx] = 2.0f * (s - g_nv[c * (CHUNK * DM) + idx]);
    else
        out[c * (CHUNK * DM) + idx] = s;
}

// ---------------- reduce dadh partials -> dh (4-way sliced, with dgelu) ----------------
__global__ void __launch_bounds__(256) reduceDh_kernel() {
    __shared__ float red[256];
    int tid = threadIdx.x;
    int slice = tid >> 6;
    int o = tid & 63;
    int idx = blockIdx.x * 64 + o;     // 512 blocks -> 32768 outputs
    const int start[4] = {0, 25, 50, 74};
    const int cnt[4] = {25, 25, 24, 24};
    float s = 0.f;
    int s0 = start[slice], n = cnt[slice];
    const float* P = g_fpart + idx;
#pragma unroll 5
    for (int sg = 0; sg < n; sg++)
        s += P[(s0 + sg) * (CHUNK * DH)];
    red[tid] = s;
    __syncthreads();
    if (slice == 0) {
        float t = red[o] + red[64 + o] + red[128 + o] + red[192 + o];
        g_dh[idx] = t * dgelu_f(g_H[idx]);
    }
}

// ---------------- fused smem-tiled updates + recall activation ----------------
// [0,392):   W2 tile 64j x 64d: W2 -= w * A^T @ dpred   (8 j-tiles x 49 d-tiles)
// [392,784): W1 tile 64k x 64j: W1 -= w * K^T @ dh      (49 k-tiles x 8 j-tiles)
// [784,912): A2 = gelu(H - w*(G@dh + colsum(dh)))       (32768 outputs)
// [912,927): biases
__global__ void __launch_bounds__(256) update_recall_kernel(const float* __restrict__ Kc, float wgt) {
    __shared__ float sU[64][68];
    __shared__ float sV[64][68];
    int tid = threadIdx.x;
    int bx = blockIdx.x;
    if (bx < 784) {
        const float* Asrc;  int alda, arow0;   // sU source: [m][row-dim]
        const float* Bsrc;  int blda, brow0;   // sV source: [m][col-dim]
        float* W;           int wld;           // output weight, leading dim
        int r0, c0;
        if (bx < 392) {
            int jt = bx / 49, dt = bx % 49;
            r0 = jt * 64; c0 = dt * 64;
            Asrc = g_A;     alda = DH; arow0 = r0;
            Bsrc = g_dpred; blda = DM; brow0 = c0;
            W = g_W2; wld = DM;
        } else {
            int b = bx - 392;
            int kt = b / 8, jt = b % 8;
            r0 = kt * 64; c0 = jt * 64;
            Asrc = Kc;   alda = DM; arow0 = r0;
            Bsrc = g_dh; blda = DH; brow0 = c0;
            W = g_W1; wld = DH;
        }
        // load sU[m][r] = Asrc[m, arow0 + r], sV[m][cc] = Bsrc[m, brow0 + cc]
        for (int i = tid; i < 1024; i += 256) {
            int m = i >> 4;
            int r4 = (i & 15) * 4;
            float4 u = *reinterpret_cast<const float4*>(Asrc + (size_t)m * alda + arow0 + r4);
            *reinterpret_cast<float4*>(&sU[m][r4]) = u;
            float4 v = *reinterpret_cast<const float4*>(Bsrc + (size_t)m * blda + brow0 + r4);
            *reinterpret_cast<float4*>(&sV[m][r4]) = v;
        }
        __syncthreads();
        int rt = (tid >> 4) * 4;
        int ct = (tid & 15) * 4;
        ull acc[4][2];
#pragma unroll
        for (int i = 0; i < 4; i++) { acc[i][0] = 0ULL; acc[i][1] = 0ULL; }
#pragma unroll 8
        for (int m = 0; m < 64; m++) {
            float4 a = *reinterpret_cast<const float4*>(&sU[m][rt]);
            ulonglong2 b = *reinterpret_cast<const ulonglong2*>(&sV[m][ct]);
            ull a0 = pk2(a.x, a.x), a1 = pk2(a.y, a.y), a2 = pk2(a.z, a.z), a3 = pk2(a.w, a.w);
            FFMA2(acc[0][0], a0, b.x); FFMA2(acc[0][1], a0, b.y);
            FFMA2(acc[1][0], a1, b.x); FFMA2(acc[1][1], a1, b.y);
            FFMA2(acc[2][0], a2, b.x); FFMA2(acc[2][1], a2, b.y);
            FFMA2(acc[3][0], a3, b.x); FFMA2(acc[3][1], a3, b.y);
        }
#pragma unroll
        for (int i = 0; i < 4; i++) {
            float* Wp = W + (size_t)(r0 + rt + i) * wld + c0 + ct;
            float4 old = *reinterpret_cast<float4*>(Wp);
            float l0, h0, l1, h1;
            upk2(l0, h0, acc[i][0]); upk2(l1, h1, acc[i][1]);
            old.x -= wgt * l0; old.y -= wgt * h0; old.z -= wgt * l1; old.w -= wgt * h1;
            *reinterpret_cast<float4*>(Wp) = old;
        }
    } else if (bx < 912) {
        int e = (bx - 784) * 256 + tid;    // 32768
        int m = e >> 9;
        int j = e & (DH - 1);
        float s = 0.f, cs = 0.f;
        const float* Gm = g_G + m * CHUNK;
#pragma unroll 8
        for (int mp = 0; mp < CHUNK; mp++) {
            float d = g_dh[mp * DH + j];
            s += Gm[mp] * d;
            cs += d;
        }
        float H2 = g_H[e] - wgt * (s + cs);
        g_A2[e] = gelu_f(H2);
    } else {
        int i = (bx - 912) * 256 + tid;    // 3840 >= 3648
        if (i < DH) {
            float s = 0.f;
#pragma unroll 8
            for (int m = 0; m < CHUNK; m++) s += g_dh[m * DH + i];
            g_b1[i] -= wgt * s;
        } else if (i < DH + DM) {
            int d = i - DH;
            float s = 0.f;
#pragma unroll 8
            for (int m = 0; m < CHUNK; m++) s += g_dpred[m * DM + d];
            g_b2[d] -= wgt * s;
        }
    }
}

// ---------------- launch ----------------
extern "C" void kernel_launch(void* const* d_in, const int* in_sizes, int n_in,
                              void* d_out, int out_size) {
    const float* x   = (const float*)d_in[0];
    const float* ckw = (const float*)d_in[1];
    const float* ckb = (const float*)d_in[2];
    const float* cvw = (const float*)d_in[3];
    const float* cvb = (const float*)d_in[4];
    const float* rsk = (const float*)d_in[5];
    const float* rsv = (const float*)d_in[6];
    const float* W1  = (const float*)d_in[7];
    const float* b1  = (const float*)d_in[8];
    const float* W2  = (const float*)d_in[9];
    const float* b2  = (const float*)d_in[10];
    float* out = (float*)d_out;

    // weights[i] = eta0*alpha^i * alpha^(CHUNK-1)/alpha^i = const
    float wgt = (float)(0.1 * pow(0.9, 63.0));

    float* nk_base;  cudaGetSymbolAddress((void**)&nk_base, g_nk);
    float* a_base;   cudaGetSymbolAddress((void**)&a_base, g_A);
    float* a2_base;  cudaGetSymbolAddress((void**)&a2_base, g_A2);
    float* dp_base;  cudaGetSymbolAddress((void**)&dp_base, g_dpred);
    float* w1_base;  cudaGetSymbolAddress((void**)&w1_base, g_W1);
    float* w2_base;  cudaGetSymbolAddress((void**)&w2_base, g_W2);
    float* fp_base;  cudaGetSymbolAddress((void**)&fp_base, g_fpart);
    float* pp_base;  cudaGetSymbolAddress((void**)&pp_base, g_ppart);

    prologue_kernel<<<2080, 256>>>(x, ckw, ckb, cvw, cvb, rsk, rsv, W1, b1, W2, b2);

    for (int c = 0; c < NCHUNK; c++) {
        const float* Kc_p = nk_base + c * (CHUNK * DM);
        // fwd: H_part = K@W1 (98 segs x 8 ntiles) + fused K@K^T
        tile_gemm_kernel<<<912, 256>>>(Kc_p, w1_base, fp_base, 8, DM, DH, DH, 0, 1);
        reduce1G_kernel<<<528, 256>>>();
        // pred: A@W2 (16 segs x 49 ntiles)
        tile_gemm_kernel<<<784, 256>>>(a_base, w2_base, pp_base, 49, DH, DM, DM, 0, 0);
        reduce2_kernel<<<784, 256>>>(c, 0, out);
        // dadh: dpred@W2^T (98 segs x 8 ntiles, transB)
        tile_gemm_kernel<<<784, 256>>>(dp_base, w2_base, fp_base, 8, DM, DM, DH, 1, 0);
        reduceDh_kernel<<<512, 256>>>();
        // fused W1/W2/bias update + A2 recall (Gram trick)
        update_recall_kernel<<<927, 256>>>(Kc_p, wgt);
        // recall pred: A2@W2'
        tile_gemm_kernel<<<784, 256>>>(a2_base, w2_base, pp_base, 49, DH, DM, DM, 0, 0);
        reduce2_kernel<<<784, 256>>>(c, 1, out);
    }
}

// round 11
// speedup vs baseline: 1.8418x; 1.0660x over previous
#include <cuda_runtime.h>
#include <math.h>

#define T_TOK 512
#define CHUNK 64
#define NCHUNK 8
#define HH 28
#define WW 28
#define CC 4
#define DM 3136
#define DH 512

#define FSEG 98    // fwd/dadh split-K segments (k = 32 each)
#define PSEG 16    // pred split-K segments (k = 32 each)
#define GSEG 8     // kgram split-K segments (k = 392 each)

typedef unsigned long long ull;

// ---------------- f32x2 helpers ----------------
__device__ __forceinline__ ull pk2(float lo, float hi) {
    ull r; asm("mov.b64 %0, {%1,%2};" : "=l"(r) : "f"(lo), "f"(hi)); return r;
}
__device__ __forceinline__ void upk2(float& lo, float& hi, ull v) {
    asm("mov.b64 {%0,%1}, %2;" : "=f"(lo), "=f"(hi) : "l"(v));
}
#define FFMA2(d, a, b) asm("fma.rn.f32x2 %0, %1, %2, %0;" : "+l"(d) : "l"(a), "l"(b))
#define ADDX2(d, a)    asm("add.rn.f32x2 %0, %0, %1;" : "+l"(d) : "l"(a))

// ---------------- device scratch ----------------
__device__ __align__(16) float g_nk[T_TOK * DM];
__device__ __align__(16) float g_nv[T_TOK * DM];
__device__ __align__(16) float g_W1[DM * DH];
__device__ __align__(16) float g_W2[DH * DM];
__device__ __align__(16) float g_b1[DH];
__device__ __align__(16) float g_b2[DM];
__device__ __align__(16) float g_H[CHUNK * DH];
__device__ __align__(16) float g_A[CHUNK * DH];
__device__ __align__(16) float g_A2[CHUNK * DH];
__device__ __align__(16) float g_dpred[CHUNK * DM];
__device__ __align__(16) float g_dh[CHUNK * DH];
__device__ __align__(16) float g_G[CHUNK * CHUNK];
__device__ __align__(16) float g_fpart[FSEG * CHUNK * DH];    // 12.8 MB (fwd & dadh partials)
__device__ __align__(16) float g_ppart[PSEG * CHUNK * DM];    // 12.8 MB (pred partials)
__device__ __align__(16) float g_gpart[GSEG * CHUNK * CHUNK];

// ---------------- math helpers ----------------
__device__ __forceinline__ float gelu_f(float x) {
    const float c = 0.7978845608028654f, a = 0.044715f;
    float u = c * (x + a * x * x * x);
    return 0.5f * x * (1.0f + tanhf(u));
}
__device__ __forceinline__ float dgelu_f(float x) {
    const float c = 0.7978845608028654f, a = 0.044715f;
    float x2 = x * x;
    float u = c * (x + a * x * x2);
    float th = tanhf(u);
    return 0.5f * (1.0f + th) + 0.5f * x * (1.0f - th * th) * c * (1.0f + 3.0f * a * x2);
}

// ---------------- prologue: conv3x3+rmsnorm and param copy ----------------
__global__ void prologue_kernel(const float* __restrict__ x,
                                const float* __restrict__ wk, const float* __restrict__ bk,
                                const float* __restrict__ wv, const float* __restrict__ bv,
                                const float* __restrict__ sk, const float* __restrict__ sv,
                                const float* __restrict__ W1, const float* __restrict__ b1,
                                const float* __restrict__ W2, const float* __restrict__ b2) {
    int tid = threadIdx.x;
    if (blockIdx.x < 1568) {
        __shared__ float swk[144], swv[144], sbk[4], sbv[4], ssk[4], ssv[4];
        if (tid < 144) { swk[tid] = wk[tid]; swv[tid] = wv[tid]; }
        if (tid < 4) { sbk[tid] = bk[tid]; sbv[tid] = bv[tid]; ssk[tid] = sk[tid]; ssv[tid] = sv[tid]; }
        __syncthreads();
        int idx = blockIdx.x * 256 + tid;   // 401408 exact
        int w = idx % WW;
        int h = (idx / WW) % HH;
        int t = idx / (HH * WW);
        float acck[4], accv[4];
#pragma unroll
        for (int o = 0; o < 4; o++) { acck[o] = sbk[o]; accv[o] = sbv[o]; }
        const float* xt = x + t * (CC * HH * WW);
#pragma unroll
        for (int kh = 0; kh < 3; kh++) {
            int hy = h + kh - 1;
            if (hy < 0 || hy >= HH) continue;
#pragma unroll
            for (int kw = 0; kw < 3; kw++) {
                int wx = w + kw - 1;
                if (wx < 0 || wx >= WW) continue;
                int wbase = (kh * 3 + kw) * 16;
#pragma unroll
                for (int ci = 0; ci < 4; ci++) {
                    float xv = xt[ci * (HH * WW) + hy * WW + wx];
#pragma unroll
                    for (int o = 0; o < 4; o++) {
                        acck[o] += xv * swk[wbase + ci * 4 + o];
                        accv[o] += xv * swv[wbase + ci * 4 + o];
                    }
                }
            }
        }
        float msk = 0.f, msv = 0.f;
#pragma unroll
        for (int o = 0; o < 4; o++) { msk += acck[o] * acck[o]; msv += accv[o] * accv[o]; }
        float ik = rsqrtf(msk * 0.25f + 1e-6f);
        float iv = rsqrtf(msv * 0.25f + 1e-6f);
        int base = t * DM + (h * WW + w) * CC;
#pragma unroll
        for (int o = 0; o < 4; o++) {
            g_nk[base + o] = acck[o] * ik * ssk[o];
            g_nv[base + o] = accv[o] * iv * ssv[o];
        }
    } else {
        int i = (blockIdx.x - 1568) * 256 + tid;   // 131072 threads
        for (int k = i; k < DM * DH; k += 131072) { g_W1[k] = W1[k]; g_W2[k] = W2[k]; }
        if (i < DH) g_b1[i] = b1[i];
        if (i < DM) g_b2[i] = b2[i];
    }
}

// ---------------- unified smem-tiled split-K GEMM, 128 thr, 8m x 4n thread tile ----------------
// blocks [0,784): Cpart[seg][m 0..63][n0g..n0g+64] = sum_{k in seg32} A[m,k]*B(k,n)
// blocks [784,1040) (kgram=1): gpart[gseg][m][n] = sum_{k in gseg392} A[m,k]*A[n,k]
__global__ void __launch_bounds__(128) tile_gemm_kernel(
    const float* __restrict__ A, const float* __restrict__ B, float* __restrict__ C,
    int ntiles, int lda, int ldb, int ntot, int transb, int kgram)
{
    if (blockIdx.x < 784) {
        __shared__ float sA[32][68];
        __shared__ float sB[32][68];
        int tid = threadIdx.x;
        int nt = blockIdx.x % ntiles;
        int seg = blockIdx.x / ntiles;
        int n0g = nt * 64;
        int k0 = seg * 32;

        // load A (64m x 32k) transposed -> sA[k][m]  (m contiguous)
#pragma unroll
        for (int i = tid; i < 512; i += 128) {
            int m = i >> 3;
            int f4 = (i & 7) * 4;
            float4 v = *reinterpret_cast<const float4*>(A + (size_t)m * lda + k0 + f4);
            sA[f4][m] = v.x; sA[f4 + 1][m] = v.y; sA[f4 + 2][m] = v.z; sA[f4 + 3][m] = v.w;
        }
        // load B tile -> sB[k][n]
        if (!transb) {
#pragma unroll
            for (int i = tid; i < 512; i += 128) {
                int k = i >> 4;
                int n4 = (i & 15) * 4;
                float4 v = *reinterpret_cast<const float4*>(B + (size_t)(k0 + k) * ldb + n0g + n4);
                *reinterpret_cast<float4*>(&sB[k][n4]) = v;
            }
        } else {
#pragma unroll
            for (int i = tid; i < 512; i += 128) {
                int n = i >> 3;
                int f4 = (i & 7) * 4;
                float4 v = *reinterpret_cast<const float4*>(B + (size_t)(n0g + n) * ldb + k0 + f4);
                sB[f4][n] = v.x; sB[f4 + 1][n] = v.y; sB[f4 + 2][n] = v.z; sB[f4 + 3][n] = v.w;
            }
        }
        __syncthreads();

        int m0 = (tid >> 4) * 8;          // 8 m-groups of 8 rows
        int n0 = (tid & 15) * 4;          // 16 n-groups of 4 cols
        ull acc[4][4];                    // [m-pair][n]: (C[m0+2mp], C[m0+2mp+1]) at col n0+n
#pragma unroll
        for (int i = 0; i < 4; i++)
#pragma unroll
            for (int j = 0; j < 4; j++) acc[i][j] = 0ULL;

#pragma unroll
        for (int kk = 0; kk < 32; kk++) {
            ulonglong2 alo = *reinterpret_cast<const ulonglong2*>(&sA[kk][m0]);      // m0..m0+3
            ulonglong2 ahi = *reinterpret_cast<const ulonglong2*>(&sA[kk][m0 + 4]);  // m0+4..m0+7
            float4 b = *reinterpret_cast<const float4*>(&sB[kk][n0]);
            ull b0 = pk2(b.x, b.x), b1 = pk2(b.y, b.y), b2 = pk2(b.z, b.z), b3 = pk2(b.w, b.w);
            FFMA2(acc[0][0], alo.x, b0); FFMA2(acc[0][1], alo.x, b1);
            FFMA2(acc[0][2], alo.x, b2); FFMA2(acc[0][3], alo.x, b3);
            FFMA2(acc[1][0], alo.y, b0); FFMA2(acc[1][1], alo.y, b1);
            FFMA2(acc[1][2], alo.y, b2); FFMA2(acc[1][3], alo.y, b3);
            FFMA2(acc[2][0], ahi.x, b0); FFMA2(acc[2][1], ahi.x, b1);
            FFMA2(acc[2][2], ahi.x, b2); FFMA2(acc[2][3], ahi.x, b3);
            FFMA2(acc[3][0], ahi.y, b0); FFMA2(acc[3][1], ahi.y, b1);
            FFMA2(acc[3][2], ahi.y, b2); FFMA2(acc[3][3], ahi.y, b3);
        }
        float* P = C + (size_t)seg * (64 * (size_t)ntot) + (size_t)m0 * ntot + n0g + n0;
#pragma unroll
        for (int mp = 0; mp < 4; mp++) {
            float e0, o0, e1, o1, e2, o2, e3, o3;
            upk2(e0, o0, acc[mp][0]); upk2(e1, o1, acc[mp][1]);
            upk2(e2, o2, acc[mp][2]); upk2(e3, o3, acc[mp][3]);
            *reinterpret_cast<float4*>(P + (size_t)(2 * mp) * ntot)     = make_float4(e0, e1, e2, e3);
            *reinterpret_cast<float4*>(P + (size_t)(2 * mp + 1) * ntot) = make_float4(o0, o1, o2, o3);
        }
    } else if (kgram) {
        // gpart[gseg][m][n] = sum over 392 k of A[m,k]*A[n,k]
        int t = (blockIdx.x - 784) * 128 + threadIdx.x;   // 32768 (256 blocks)
        int gseg = t >> 12;                // 0..7
        int o = t & 4095;
        int m = o >> 6;
        int n = o & 63;
        int kbase = gseg * 392;
        const ull* pa = reinterpret_cast<const ull*>(A + (size_t)m * DM + kbase);
        const ull* pb = reinterpret_cast<const ull*>(A + (size_t)n * DM + kbase);
        ull acc2 = 0ULL;
#pragma unroll 8
        for (int k2 = 0; k2 < 196; k2++) FFMA2(acc2, pa[k2], pb[k2]);
        float lo, hi;
        upk2(lo, hi, acc2);
        g_gpart[gseg * 4096 + o] = lo + hi;
    }
}

// ---------------- reduce fwd partials -> H, A (4-way sliced) ; and G ----------------
__global__ void __launch_bounds__(256) reduce1G_kernel() {
    if (blockIdx.x < 512) {
        __shared__ float red[256];
        int tid = threadIdx.x;
        int slice = tid >> 6;              // 0..3
        int o = tid & 63;
        int idx = blockIdx.x * 64 + o;     // 0..32767
        const int start[4] = {0, 25, 50, 74};
        const int cnt[4] = {25, 25, 24, 24};
        float s = 0.f;
        int s0 = start[slice], n = cnt[slice];
        const float* P = g_fpart + idx;
#pragma unroll 5
        for (int sg = 0; sg < n; sg++)
            s += P[(s0 + sg) * (CHUNK * DH)];
        red[tid] = s;
        __syncthreads();
        if (slice == 0) {
            float t = red[o] + red[64 + o] + red[128 + o] + red[192 + o] + g_b1[idx & (DH - 1)];
            g_H[idx] = t;
            g_A[idx] = gelu_f(t);
        }
    } else {
        int t = (blockIdx.x - 512) * 256 + threadIdx.x;   // 4096
        float s = 0.f;
#pragma unroll
        for (int sg = 0; sg < GSEG; sg++) s += g_gpart[sg * 4096 + t];
        g_G[t] = s;
    }
}

// ---------------- reduce pred partials (float4/f32x2): mode0 -> dpred, mode1 -> out ----------------
__global__ void __launch_bounds__(256) reduce2_kernel(int c, int mode, float* __restrict__ out) {
    int f = blockIdx.x * 256 + threadIdx.x;    // 196 blocks = 50176
    int idx4 = f * 4;
    int d0 = idx4 % DM;
    ulonglong2 s = *reinterpret_cast<const ulonglong2*>(&g_b2[d0]);
#pragma unroll
    for (int sg = 0; sg < PSEG; sg++) {
        ulonglong2 p = *reinterpret_cast<const ulonglong2*>(&g_ppart[sg * (CHUNK * DM) + idx4]);
        ADDX2(s.x, p.x);
        ADDX2(s.y, p.y);
    }
    float s0, s1, s2, s3;
    upk2(s0, s1, s.x); upk2(s2, s3, s.y);
    if (mode == 0) {
        float4 v = *reinterpret_cast<const float4*>(&g_nv[c * (CHUNK * DM) + idx4]);
        *reinterpret_cast<float4*>(&g_dpred[idx4]) =
            make_float4(2.f * (s0 - v.x), 2.f * (s1 - v.y), 2.f * (s2 - v.z), 2.f * (s3 - v.w));
    } else {
        *reinterpret_cast<float4*>(&out[c * (CHUNK * DM) + idx4]) = make_float4(s0, s1, s2, s3);
    }
}

// ---------------- reduce dadh partials -> dh (4-way sliced, with dgelu) ----------------
__global__ void __launch_bounds__(256) reduceDh_kernel() {
    __shared__ float red[256];
    int tid = threadIdx.x;
    int slice = tid >> 6;
    int o = tid & 63;
    int idx = blockIdx.x * 64 + o;     // 512 blocks -> 32768 outputs
    const int start[4] = {0, 25, 50, 74};
    const int cnt[4] = {25, 25, 24, 24};
    float s = 0.f;
    int s0 = start[slice], n = cnt[slice];
    const float* P = g_fpart + idx;
#pragma unroll 5
    for (int sg = 0; sg < n; sg++)
        s += P[(s0 + sg) * (CHUNK * DH)];
    red[tid] = s;
    __syncthreads();
    if (slice == 0) {
        float t = red[o] + red[64 + o] + red[128 + o] + red[192 + o];
        g_dh[idx] = t * dgelu_f(g_H[idx]);
    }
}

// ---------------- fused smem-tiled updates + recall activation (128 thr) ----------------
// [0,392):      W2 tile 64j x 64d: W2 -= w * A^T @ dpred   (8 j-tiles x 49 d-tiles)
// [392,784):    W1 tile 64k x 64j: W1 -= w * K^T @ dh      (49 k-tiles x 8 j-tiles)
// [784,1040):   A2 = gelu(H - w*(G@dh + colsum(dh)))       (32768 outputs)
// [1040,1069):  biases
__global__ void __launch_bounds__(128) update_recall_kernel(const float* __restrict__ Kc, float wgt) {
    __shared__ float sU[64][68];
    __shared__ float sV[64][68];
    int tid = threadIdx.x;
    int bx = blockIdx.x;
    if (bx < 784) {
        const float* Asrc;  int alda;
        const float* Bsrc;  int blda;
        float* W;           int wld;
        int r0, c0;
        if (bx < 392) {
            int jt = bx / 49, dt = bx % 49;
            r0 = jt * 64; c0 = dt * 64;
            Asrc = g_A;     alda = DH;
            Bsrc = g_dpred; blda = DM;
            W = g_W2; wld = DM;
        } else {
            int b = bx - 392;
            int kt = b / 8, jt = b % 8;
            r0 = kt * 64; c0 = jt * 64;
            Asrc = Kc;   alda = DM;
            Bsrc = g_dh; blda = DH;
            W = g_W1; wld = DH;
        }
        // sU[m][r] = Asrc[m, r0+r], sV[m][cc] = Bsrc[m, c0+cc]
#pragma unroll
        for (int i = tid; i < 1024; i += 128) {
            int m = i >> 4;
            int r4 = (i & 15) * 4;
            float4 u = *reinterpret_cast<const float4*>(Asrc + (size_t)m * alda + r0 + r4);
            *reinterpret_cast<float4*>(&sU[m][r4]) = u;
            float4 v = *reinterpret_cast<const float4*>(Bsrc + (size_t)m * blda + c0 + r4);
            *reinterpret_cast<float4*>(&sV[m][r4]) = v;
        }
        __syncthreads();
        int rt = (tid >> 4) * 8;
        int ct = (tid & 15) * 4;
        ull acc[4][4];
#pragma unroll
        for (int i = 0; i < 4; i++)
#pragma unroll
            for (int j = 0; j < 4; j++) acc[i][j] = 0ULL;
#pragma unroll 8
        for (int m = 0; m < 64; m++) {
            ulonglong2 alo = *reinterpret_cast<const ulonglong2*>(&sU[m][rt]);
            ulonglong2 ahi = *reinterpret_cast<const ulonglong2*>(&sU[m][rt + 4]);
            float4 b = *reinterpret_cast<const float4*>(&sV[m][ct]);
            ull b0 = pk2(b.x, b.x), b1 = pk2(b.y, b.y), b2 = pk2(b.z, b.z), b3 = pk2(b.w, b.w);
            FFMA2(acc[0][0], alo.x, b0); FFMA2(acc[0][1], alo.x, b1);
            FFMA2(acc[0][2], alo.x, b2); FFMA2(acc[0][3], alo.x, b3);
            FFMA2(acc[1][0], alo.y, b0); FFMA2(acc[1][1], alo.y, b1);
            FFMA2(acc[1][2], alo.y, b2); FFMA2(acc[1][3], alo.y, b3);
            FFMA2(acc[2][0], ahi.x, b0); FFMA2(acc[2][1], ahi.x, b1);
            FFMA2(acc[2][2], ahi.x, b2); FFMA2(acc[2][3], ahi.x, b3);
            FFMA2(acc[3][0], ahi.y, b0); FFMA2(acc[3][1], ahi.y, b1);
            FFMA2(acc[3][2], ahi.y, b2); FFMA2(acc[3][3], ahi.y, b3);
        }
#pragma unroll
        for (int mp = 0; mp < 4; mp++) {
            float e0, o0, e1, o1, e2, o2, e3, o3;
            upk2(e0, o0, acc[mp][0]); upk2(e1, o1, acc[mp][1]);
            upk2(e2, o2, acc[mp][2]); upk2(e3, o3, acc[mp][3]);
            float* We = W + (size_t)(r0 + rt + 2 * mp) * wld + c0 + ct;
            float4 olde = *reinterpret_cast<float4*>(We);
            olde.x -= wgt * e0; olde.y -= wgt * e1; olde.z -= wgt * e2; olde.w -= wgt * e3;
            *reinterpret_cast<float4*>(We) = olde;
            float* Wo = W + (size_t)(r0 + rt + 2 * mp + 1) * wld + c0 + ct;
            float4 oldo = *reinterpret_cast<float4*>(Wo);
            oldo.x -= wgt * o0; oldo.y -= wgt * o1; oldo.z -= wgt * o2; oldo.w -= wgt * o3;
            *reinterpret_cast<float4*>(Wo) = oldo;
        }
    } else if (bx < 1040) {
        int e = (bx - 784) * 128 + tid;    // 32768
        int m = e >> 9;
        int j = e & (DH - 1);
        float s = 0.f, cs = 0.f;
        const float* Gm = g_G + m * CHUNK;
#pragma unroll 8
        for (int mp = 0; mp < CHUNK; mp++) {
            float d = g_dh[mp * DH + j];
            s += Gm[mp] * d;
            cs += d;
        }
        float H2 = g_H[e] - wgt * (s + cs);
        g_A2[e] = gelu_f(H2);
    } else {
        int i = (bx - 1040) * 128 + tid;   // 3712 >= 3648
        if (i < DH) {
            float s = 0.f;
#pragma unroll 8
            for (int m = 0; m < CHUNK; m++) s += g_dh[m * DH + i];
            g_b1[i] -= wgt * s;
        } else if (i < DH + DM) {
            int d = i - DH;
            float s = 0.f;
#pragma unroll 8
            for (int m = 0; m < CHUNK; m++) s += g_dpred[m * DM + d];
            g_b2[d] -= wgt * s;
        }
    }
}

// ---------------- launch ----------------
extern "C" void kernel_launch(void* const* d_in, const int* in_sizes, int n_in,
                              void* d_out, int out_size) {
    const float* x   = (const float*)d_in[0];
    const float* ckw = (const float*)d_in[1];
    const float* ckb = (const float*)d_in[2];
    const float* cvw = (const float*)d_in[3];
    const float* cvb = (const float*)d_in[4];
    const float* rsk = (const float*)d_in[5];
    const float* rsv = (const float*)d_in[6];
    const float* W1  = (const float*)d_in[7];
    const float* b1  = (const float*)d_in[8];
    const float* W2  = (const float*)d_in[9];
    const float* b2  = (const float*)d_in[10];
    float* out = (float*)d_out;

    // weights[i] = eta0*alpha^i * alpha^(CHUNK-1)/alpha^i = const
    float wgt = (float)(0.1 * pow(0.9, 63.0));

    float* nk_base;  cudaGetSymbolAddress((void**)&nk_base, g_nk);
    float* a_base;   cudaGetSymbolAddress((void**)&a_base, g_A);
    float* a2_base;  cudaGetSymbolAddress((void**)&a2_base, g_A2);
    float* dp_base;  cudaGetSymbolAddress((void**)&dp_base, g_dpred);
    float* w1_base;  cudaGetSymbolAddress((void**)&w1_base, g_W1);
    float* w2_base;  cudaGetSymbolAddress((void**)&w2_base, g_W2);
    float* fp_base;  cudaGetSymbolAddress((void**)&fp_base, g_fpart);
    float* pp_base;  cudaGetSymbolAddress((void**)&pp_base, g_ppart);

    prologue_kernel<<<2080, 256>>>(x, ckw, ckb, cvw, cvb, rsk, rsv, W1, b1, W2, b2);

    for (int c = 0; c < NCHUNK; c++) {
        const float* Kc_p = nk_base + c * (CHUNK * DM);
        // fwd: H_part = K@W1 (98 segs x 8 ntiles) + fused K@K^T
        tile_gemm_kernel<<<1040, 128>>>(Kc_p, w1_base, fp_base, 8, DM, DH, DH, 0, 1);
        reduce1G_kernel<<<528, 256>>>();
        // pred: A@W2 (16 segs x 49 ntiles)
        tile_gemm_kernel<<<784, 128>>>(a_base, w2_base, pp_base, 49, DH, DM, DM, 0, 0);
        reduce2_kernel<<<196, 256>>>(c, 0, out);
        // dadh: dpred@W2^T (98 segs x 8 ntiles, transB)
        tile_gemm_kernel<<<784, 128>>>(dp_base, w2_base, fp_base, 8, DM, DM, DH, 1, 0);
        reduceDh_kernel<<<512, 256>>>();
        // fused W1/W2/bias update + A2 recall (Gram trick)
        update_recall_kernel<<<1069, 128>>>(Kc_p, wgt);
        // recall pred: A2@W2'
        tile_gemm_kernel<<<784, 128>>>(a2_base, w2_base, pp_base, 49, DH, DM, DM, 0, 0);
        reduce2_kernel<<<196, 256>>>(c, 1, out);
    }
}

// round 12
// speedup vs baseline: 2.0422x; 1.1088x over previous
#include <cuda_runtime.h>
#include <math.h>

#define T_TOK 512
#define CHUNK 64
#define NCHUNK 8
#define HH 28
#define WW 28
#define CC 4
#define DM 3136
#define DH 512

#define FSEG 98    // fwd/dadh split-K segments (k = 32 each)
#define PSEG 16    // pred split-K segments (k = 32 each)
#define GSEG 8     // kgram split-K segments (k = 392 each)

typedef unsigned long long ull;

// ---------------- f32x2 helpers ----------------
__device__ __forceinline__ ull pk2(float lo, float hi) {
    ull r; asm("mov.b64 %0, {%1,%2};" : "=l"(r) : "f"(lo), "f"(hi)); return r;
}
__device__ __forceinline__ void upk2(float& lo, float& hi, ull v) {
    asm("mov.b64 {%0,%1}, %2;" : "=f"(lo), "=f"(hi) : "l"(v));
}
#define FFMA2(d, a, b) asm("fma.rn.f32x2 %0, %1, %2, %0;" : "+l"(d) : "l"(a), "l"(b))
#define ADDX2(d, a)    asm("add.rn.f32x2 %0, %0, %1;" : "+l"(d) : "l"(a))

// ---------------- device scratch ----------------
__device__ __align__(16) float g_nk[T_TOK * DM];
__device__ __align__(16) float g_nv[T_TOK * DM];
__device__ __align__(16) float g_W1[DM * DH];
__device__ __align__(16) float g_W2[DH * DM];
__device__ __align__(16) float g_b1[DH];
__device__ __align__(16) float g_b2[DM];
__device__ __align__(16) float g_H[CHUNK * DH];
__device__ __align__(16) float g_A[CHUNK * DH];
__device__ __align__(16) float g_A2[CHUNK * DH];
__device__ __align__(16) float g_dpred[CHUNK * DM];
__device__ __align__(16) float g_dh[CHUNK * DH];
__device__ __align__(16) float g_G[CHUNK * CHUNK];
__device__ __align__(16) float g_fpart[FSEG * CHUNK * DH];    // 12.8 MB (fwd & dadh partials)
__device__ __align__(16) float g_ppart[PSEG * CHUNK * DM];    // 12.8 MB (pred/recall partials)
__device__ __align__(16) float g_gpart[GSEG * CHUNK * CHUNK];

// ---------------- math helpers ----------------
__device__ __forceinline__ float gelu_f(float x) {
    const float c = 0.7978845608028654f, a = 0.044715f;
    float u = c * (x + a * x * x * x);
    return 0.5f * x * (1.0f + tanhf(u));
}
__device__ __forceinline__ float dgelu_f(float x) {
    const float c = 0.7978845608028654f, a = 0.044715f;
    float x2 = x * x;
    float u = c * (x + a * x * x2);
    float th = tanhf(u);
    return 0.5f * (1.0f + th) + 0.5f * x * (1.0f - th * th) * c * (1.0f + 3.0f * a * x2);
}

// ---------------- prologue: conv3x3+rmsnorm and param copy ----------------
__global__ void prologue_kernel(const float* __restrict__ x,
                                const float* __restrict__ wk, const float* __restrict__ bk,
                                const float* __restrict__ wv, const float* __restrict__ bv,
                                const float* __restrict__ sk, const float* __restrict__ sv,
                                const float* __restrict__ W1, const float* __restrict__ b1,
                                const float* __restrict__ W2, const float* __restrict__ b2) {
    int tid = threadIdx.x;
    if (blockIdx.x < 1568) {
        __shared__ float swk[144], swv[144], sbk[4], sbv[4], ssk[4], ssv[4];
        if (tid < 144) { swk[tid] = wk[tid]; swv[tid] = wv[tid]; }
        if (tid < 4) { sbk[tid] = bk[tid]; sbv[tid] = bv[tid]; ssk[tid] = sk[tid]; ssv[tid] = sv[tid]; }
        __syncthreads();
        int idx = blockIdx.x * 256 + tid;   // 401408 exact
        int w = idx % WW;
        int h = (idx / WW) % HH;
        int t = idx / (HH * WW);
        float acck[4], accv[4];
#pragma unroll
        for (int o = 0; o < 4; o++) { acck[o] = sbk[o]; accv[o] = sbv[o]; }
        const float* xt = x + t * (CC * HH * WW);
#pragma unroll
        for (int kh = 0; kh < 3; kh++) {
            int hy = h + kh - 1;
            if (hy < 0 || hy >= HH) continue;
#pragma unroll
            for (int kw = 0; kw < 3; kw++) {
                int wx = w + kw - 1;
                if (wx < 0 || wx >= WW) continue;
                int wbase = (kh * 3 + kw) * 16;
#pragma unroll
                for (int ci = 0; ci < 4; ci++) {
                    float xv = xt[ci * (HH * WW) + hy * WW + wx];
#pragma unroll
                    for (int o = 0; o < 4; o++) {
                        acck[o] += xv * swk[wbase + ci * 4 + o];
                        accv[o] += xv * swv[wbase + ci * 4 + o];
                    }
                }
            }
        }
        float msk = 0.f, msv = 0.f;
#pragma unroll
        for (int o = 0; o < 4; o++) { msk += acck[o] * acck[o]; msv += accv[o] * accv[o]; }
        float ik = rsqrtf(msk * 0.25f + 1e-6f);
        float iv = rsqrtf(msv * 0.25f + 1e-6f);
        int base = t * DM + (h * WW + w) * CC;
#pragma unroll
        for (int o = 0; o < 4; o++) {
            g_nk[base + o] = acck[o] * ik * ssk[o];
            g_nv[base + o] = accv[o] * iv * ssv[o];
        }
    } else {
        int i = (blockIdx.x - 1568) * 256 + tid;   // 131072 threads
        for (int k = i; k < DM * DH; k += 131072) { g_W1[k] = W1[k]; g_W2[k] = W2[k]; }
        if (i < DH) g_b1[i] = b1[i];
        if (i < DM) g_b2[i] = b2[i];
    }
}

// ---------------- GEMM tile body (64m x 64n x 32k, 128 thr, 8m x 4n/thread) ----------------
__device__ __forceinline__ void gemm_body(
    const float* __restrict__ A, const float* __restrict__ B, float* __restrict__ C,
    int bx, int ntiles, int lda, int ldb, int ntot, int transb,
    float (&sA)[32][68], float (&sB)[32][68])
{
    int tid = threadIdx.x;
    int nt = bx % ntiles;
    int seg = bx / ntiles;
    int n0g = nt * 64;
    int k0 = seg * 32;

    // load A (64m x 32k) transposed -> sA[k][m]  (m contiguous)
#pragma unroll
    for (int i = tid; i < 512; i += 128) {
        int m = i >> 3;
        int f4 = (i & 7) * 4;
        float4 v = *reinterpret_cast<const float4*>(A + (size_t)m * lda + k0 + f4);
        sA[f4][m] = v.x; sA[f4 + 1][m] = v.y; sA[f4 + 2][m] = v.z; sA[f4 + 3][m] = v.w;
    }
    // load B tile -> sB[k][n]
    if (!transb) {
#pragma unroll
        for (int i = tid; i < 512; i += 128) {
            int k = i >> 4;
            int n4 = (i & 15) * 4;
            float4 v = *reinterpret_cast<const float4*>(B + (size_t)(k0 + k) * ldb + n0g + n4);
            *reinterpret_cast<float4*>(&sB[k][n4]) = v;
        }
    } else {
#pragma unroll
        for (int i = tid; i < 512; i += 128) {
            int n = i >> 3;
            int f4 = (i & 7) * 4;
            float4 v = *reinterpret_cast<const float4*>(B + (size_t)(n0g + n) * ldb + k0 + f4);
            sB[f4][n] = v.x; sB[f4 + 1][n] = v.y; sB[f4 + 2][n] = v.z; sB[f4 + 3][n] = v.w;
        }
    }
    __syncthreads();

    int m0 = (tid >> 4) * 8;
    int n0 = (tid & 15) * 4;
    ull acc[4][4];
#pragma unroll
    for (int i = 0; i < 4; i++)
#pragma unroll
        for (int j = 0; j < 4; j++) acc[i][j] = 0ULL;

#pragma unroll
    for (int kk = 0; kk < 32; kk++) {
        ulonglong2 alo = *reinterpret_cast<const ulonglong2*>(&sA[kk][m0]);
        ulonglong2 ahi = *reinterpret_cast<const ulonglong2*>(&sA[kk][m0 + 4]);
        float4 b = *reinterpret_cast<const float4*>(&sB[kk][n0]);
        ull b0 = pk2(b.x, b.x), b1 = pk2(b.y, b.y), b2 = pk2(b.z, b.z), b3 = pk2(b.w, b.w);
        FFMA2(acc[0][0], alo.x, b0); FFMA2(acc[0][1], alo.x, b1);
        FFMA2(acc[0][2], alo.x, b2); FFMA2(acc[0][3], alo.x, b3);
        FFMA2(acc[1][0], alo.y, b0); FFMA2(acc[1][1], alo.y, b1);
        FFMA2(acc[1][2], alo.y, b2); FFMA2(acc[1][3], alo.y, b3);
        FFMA2(acc[2][0], ahi.x, b0); FFMA2(acc[2][1], ahi.x, b1);
        FFMA2(acc[2][2], ahi.x, b2); FFMA2(acc[2][3], ahi.x, b3);
        FFMA2(acc[3][0], ahi.y, b0); FFMA2(acc[3][1], ahi.y, b1);
        FFMA2(acc[3][2], ahi.y, b2); FFMA2(acc[3][3], ahi.y, b3);
    }
    float* P = C + (size_t)seg * (64 * (size_t)ntot) + (size_t)m0 * ntot + n0g + n0;
#pragma unroll
    for (int mp = 0; mp < 4; mp++) {
        float e0, o0, e1, o1, e2, o2, e3, o3;
        upk2(e0, o0, acc[mp][0]); upk2(e1, o1, acc[mp][1]);
        upk2(e2, o2, acc[mp][2]); upk2(e3, o3, acc[mp][3]);
        *reinterpret_cast<float4*>(P + (size_t)(2 * mp) * ntot)     = make_float4(e0, e1, e2, e3);
        *reinterpret_cast<float4*>(P + (size_t)(2 * mp + 1) * ntot) = make_float4(o0, o1, o2, o3);
    }
}

// ---------------- stage1: fwd (K@W1) + kgram + prev-chunk recall pred (A2@W2) ----------------
// do_fwd: blocks [0,784) fwd, [784,1040) kgram, [1040,1824) recall (if do_recall)
// !do_fwd (epilogue): blocks [0,784) recall
__global__ void __launch_bounds__(128) stage1_kernel(const float* __restrict__ Kc,
                                                     int do_fwd, int do_recall) {
    __shared__ float sA[32][68];
    __shared__ float sB[32][68];
    int bx = blockIdx.x;
    if (do_fwd) {
        if (bx < 784) {
            gemm_body(Kc, g_W1, g_fpart, bx, 8, DM, DH, DH, 0, sA, sB);
            return;
        }
        if (bx < 1040) {
            int t = (bx - 784) * 128 + threadIdx.x;   // 32768
            int gseg = t >> 12;
            int o = t & 4095;
            int m = o >> 6;
            int n = o & 63;
            int kbase = gseg * 392;
            const ull* pa = reinterpret_cast<const ull*>(Kc + (size_t)m * DM + kbase);
            const ull* pb = reinterpret_cast<const ull*>(Kc + (size_t)n * DM + kbase);
            ull acc2 = 0ULL;
#pragma unroll 8
            for (int k2 = 0; k2 < 196; k2++) FFMA2(acc2, pa[k2], pb[k2]);
            float lo, hi;
            upk2(lo, hi, acc2);
            g_gpart[gseg * 4096 + o] = lo + hi;
            return;
        }
        if (do_recall)
            gemm_body(g_A2, g_W2, g_ppart, bx - 1040, 49, DH, DM, DM, 0, sA, sB);
    } else {
        gemm_body(g_A2, g_W2, g_ppart, bx, 49, DH, DM, DM, 0, sA, sB);
    }
}

// ---------------- stage2: reduce fwd partials -> H,A ; G ; prev-chunk out-write ----------------
// do_main: blocks [0,512) H/A, [512,528) G, out region at 528; else out region at 0
__global__ void __launch_bounds__(256) stage2_kernel(int do_main, int do_out, int c_out,
                                                     float* __restrict__ out) {
    int bx = blockIdx.x;
    int obase = do_main ? 528 : 0;
    if (do_main && bx < 512) {
        __shared__ float red[256];
        int tid = threadIdx.x;
        int slice = tid >> 6;
        int o = tid & 63;
        int idx = bx * 64 + o;
        const int start[4] = {0, 25, 50, 74};
        const int cnt[4] = {25, 25, 24, 24};
        float s = 0.f;
        int s0 = start[slice], n = cnt[slice];
        const float* P = g_fpart + idx;
#pragma unroll 5
        for (int sg = 0; sg < n; sg++)
            s += P[(s0 + sg) * (CHUNK * DH)];
        red[tid] = s;
        __syncthreads();
        if (slice == 0) {
            float t = red[o] + red[64 + o] + red[128 + o] + red[192 + o] + g_b1[idx & (DH - 1)];
            g_H[idx] = t;
            g_A[idx] = gelu_f(t);
        }
    } else if (do_main && bx < 528) {
        int t = (bx - 512) * 256 + threadIdx.x;
        float s = 0.f;
#pragma unroll
        for (int sg = 0; sg < GSEG; sg++) s += g_gpart[sg * 4096 + t];
        g_G[t] = s;
    } else if (do_out) {
        int f = (bx - obase) * 256 + threadIdx.x;   // 196 blocks = 50176
        int idx4 = f * 4;
        int d0 = idx4 % DM;
        ulonglong2 s = *reinterpret_cast<const ulonglong2*>(&g_b2[d0]);
#pragma unroll
        for (int sg = 0; sg < PSEG; sg++) {
            ulonglong2 p = *reinterpret_cast<const ulonglong2*>(&g_ppart[sg * (CHUNK * DM) + idx4]);
            ADDX2(s.x, p.x);
            ADDX2(s.y, p.y);
        }
        float s0, s1, s2, s3;
        upk2(s0, s1, s.x); upk2(s2, s3, s.y);
        *reinterpret_cast<float4*>(&out[c_out * (CHUNK * DM) + idx4]) = make_float4(s0, s1, s2, s3);
    }
}

// ---------------- pred GEMM: A@W2 or A2@W2 -> ppart ----------------
__global__ void __launch_bounds__(128) pred_gemm_kernel(const float* __restrict__ Asrc) {
    __shared__ float sA[32][68];
    __shared__ float sB[32][68];
    gemm_body(Asrc, g_W2, g_ppart, blockIdx.x, 49, DH, DM, DM, 0, sA, sB);
}

// ---------------- dadh GEMM: dpred@W2^T -> fpart ----------------
__global__ void __launch_bounds__(128) dadh_gemm_kernel() {
    __shared__ float sA[32][68];
    __shared__ float sB[32][68];
    gemm_body(g_dpred, g_W2, g_fpart, blockIdx.x, 8, DM, DM, DH, 1, sA, sB);
}

// ---------------- reduce pred partials -> dpred ----------------
__global__ void __launch_bounds__(256) reduce2_kernel(int c) {
    int f = blockIdx.x * 256 + threadIdx.x;    // 196 blocks = 50176
    int idx4 = f * 4;
    int d0 = idx4 % DM;
    ulonglong2 s = *reinterpret_cast<const ulonglong2*>(&g_b2[d0]);
#pragma unroll
    for (int sg = 0; sg < PSEG; sg++) {
        ulonglong2 p = *reinterpret_cast<const ulonglong2*>(&g_ppart[sg * (CHUNK * DM) + idx4]);
        ADDX2(s.x, p.x);
        ADDX2(s.y, p.y);
    }
    float s0, s1, s2, s3;
    upk2(s0, s1, s.x); upk2(s2, s3, s.y);
    float4 v = *reinterpret_cast<const float4*>(&g_nv[c * (CHUNK * DM) + idx4]);
    *reinterpret_cast<float4*>(&g_dpred[idx4]) =
        make_float4(2.f * (s0 - v.x), 2.f * (s1 - v.y), 2.f * (s2 - v.z), 2.f * (s3 - v.w));
}

// ---------------- reduce dadh partials -> dh (4-way sliced, with dgelu) ----------------
__global__ void __launch_bounds__(256) reduceDh_kernel() {
    __shared__ float red[256];
    int tid = threadIdx.x;
    int slice = tid >> 6;
    int o = tid & 63;
    int idx = blockIdx.x * 64 + o;     // 512 blocks -> 32768 outputs
    const int start[4] = {0, 25, 50, 74};
    const int cnt[4] = {25, 25, 24, 24};
    float s = 0.f;
    int s0 = start[slice], n = cnt[slice];
    const float* P = g_fpart + idx;
#pragma unroll 5
    for (int sg = 0; sg < n; sg++)
        s += P[(s0 + sg) * (CHUNK * DH)];
    red[tid] = s;
    __syncthreads();
    if (slice == 0) {
        float t = red[o] + red[64 + o] + red[128 + o] + red[192 + o];
        g_dh[idx] = t * dgelu_f(g_H[idx]);
    }
}

// ---------------- fused smem-tiled updates + recall activation (128 thr) ----------------
// [0,392):      W2 -= w * A^T @ dpred   (8 j-tiles x 49 d-tiles)
// [392,784):    W1 -= w * K^T @ dh      (49 k-tiles x 8 j-tiles)
// [784,1040):   A2 = gelu(H - w*(G@dh + colsum(dh)))
// [1040,1069):  biases
__global__ void __launch_bounds__(128) update_recall_kernel(const float* __restrict__ Kc, float wgt) {
    __shared__ float sU[64][68];
    __shared__ float sV[64][68];
    int tid = threadIdx.x;
    int bx = blockIdx.x;
    if (bx < 784) {
        const float* Asrc;  int alda;
        const float* Bsrc;  int blda;
        float* W;           int wld;
        int r0, c0;
        if (bx < 392) {
            int jt = bx / 49, dt = bx % 49;
            r0 = jt * 64; c0 = dt * 64;
            Asrc = g_A;     alda = DH;
            Bsrc = g_dpred; blda = DM;
            W = g_W2; wld = DM;
        } else {
            int b = bx - 392;
            int kt = b / 8, jt = b % 8;
            r0 = kt * 64; c0 = jt * 64;
            Asrc = Kc;   alda = DM;
            Bsrc = g_dh; blda = DH;
            W = g_W1; wld = DH;
        }
#pragma unroll
        for (int i = tid; i < 1024; i += 128) {
            int m = i >> 4;
            int r4 = (i & 15) * 4;
            float4 u = *reinterpret_cast<const float4*>(Asrc + (size_t)m * alda + r0 + r4);
            *reinterpret_cast<float4*>(&sU[m][r4]) = u;
            float4 v = *reinterpret_cast<const float4*>(Bsrc + (size_t)m * blda + c0 + r4);
            *reinterpret_cast<float4*>(&sV[m][r4]) = v;
        }
        __syncthreads();
        int rt = (tid >> 4) * 8;
        int ct = (tid & 15) * 4;
        ull acc[4][4];
#pragma unroll
        for (int i = 0; i < 4; i++)
#pragma unroll
            for (int j = 0; j < 4; j++) acc[i][j] = 0ULL;
#pragma unroll 8
        for (int m = 0; m < 64; m++) {
            ulonglong2 alo = *reinterpret_cast<const ulonglong2*>(&sU[m][rt]);
            ulonglong2 ahi = *reinterpret_cast<const ulonglong2*>(&sU[m][rt + 4]);
            float4 b = *reinterpret_cast<const float4*>(&sV[m][ct]);
            ull b0 = pk2(b.x, b.x), b1 = pk2(b.y, b.y), b2 = pk2(b.z, b.z), b3 = pk2(b.w, b.w);
            FFMA2(acc[0][0], alo.x, b0); FFMA2(acc[0][1], alo.x, b1);
            FFMA2(acc[0][2], alo.x, b2); FFMA2(acc[0][3], alo.x, b3);
            FFMA2(acc[1][0], alo.y, b0); FFMA2(acc[1][1], alo.y, b1);
            FFMA2(acc[1][2], alo.y, b2); FFMA2(acc[1][3], alo.y, b3);
            FFMA2(acc[2][0], ahi.x, b0); FFMA2(acc[2][1], ahi.x, b1);
            FFMA2(acc[2][2], ahi.x, b2); FFMA2(acc[2][3], ahi.x, b3);
            FFMA2(acc[3][0], ahi.y, b0); FFMA2(acc[3][1], ahi.y, b1);
            FFMA2(acc[3][2], ahi.y, b2); FFMA2(acc[3][3], ahi.y, b3);
        }
#pragma unroll
        for (int mp = 0; mp < 4; mp++) {
            float e0, o0, e1, o1, e2, o2, e3, o3;
            upk2(e0, o0, acc[mp][0]); upk2(e1, o1, acc[mp][1]);
            upk2(e2, o2, acc[mp][2]); upk2(e3, o3, acc[mp][3]);
            float* We = W + (size_t)(r0 + rt + 2 * mp) * wld + c0 + ct;
            float4 olde = *reinterpret_cast<float4*>(We);
            olde.x -= wgt * e0; olde.y -= wgt * e1; olde.z -= wgt * e2; olde.w -= wgt * e3;
            *reinterpret_cast<float4*>(We) = olde;
            float* Wo = W + (size_t)(r0 + rt + 2 * mp + 1) * wld + c0 + ct;
            float4 oldo = *reinterpret_cast<float4*>(Wo);
            oldo.x -= wgt * o0; oldo.y -= wgt * o1; oldo.z -= wgt * o2; oldo.w -= wgt * o3;
            *reinterpret_cast<float4*>(Wo) = oldo;
        }
    } else if (bx < 1040) {
        int e = (bx - 784) * 128 + tid;    // 32768
        int m = e >> 9;
        int j = e & (DH - 1);
        float s = 0.f, cs = 0.f;
        const float* Gm = g_G + m * CHUNK;
#pragma unroll 8
        for (int mp = 0; mp < CHUNK; mp++) {
            float d = g_dh[mp * DH + j];
            s += Gm[mp] * d;
            cs += d;
        }
        float H2 = g_H[e] - wgt * (s + cs);
        g_A2[e] = gelu_f(H2);
    } else {
        int i = (bx - 1040) * 128 + tid;   // 3712 >= 3648
        if (i < DH) {
            float s = 0.f;
#pragma unroll 8
            for (int m = 0; m < CHUNK; m++) s += g_dh[m * DH + i];
            g_b1[i] -= wgt * s;
        } else if (i < DH + DM) {
            int d = i - DH;
            float s = 0.f;
#pragma unroll 8
            for (int m = 0; m < CHUNK; m++) s += g_dpred[m * DM + d];
            g_b2[d] -= wgt * s;
        }
    }
}

// ---------------- launch ----------------
extern "C" void kernel_launch(void* const* d_in, const int* in_sizes, int n_in,
                              void* d_out, int out_size) {
    const float* x   = (const float*)d_in[0];
    const float* ckw = (const float*)d_in[1];
    const float* ckb = (const float*)d_in[2];
    const float* cvw = (const float*)d_in[3];
    const float* cvb = (const float*)d_in[4];
    const float* rsk = (const float*)d_in[5];
    const float* rsv = (const float*)d_in[6];
    const float* W1  = (const float*)d_in[7];
    const float* b1  = (const float*)d_in[8];
    const float* W2  = (const float*)d_in[9];
    const float* b2  = (const float*)d_in[10];
    float* out = (float*)d_out;

    // weights[i] = eta0*alpha^i * alpha^(CHUNK-1)/alpha^i = const
    float wgt = (float)(0.1 * pow(0.9, 63.0));

    float* nk_base;  cudaGetSymbolAddress((void**)&nk_base, g_nk);
    float* a_base;   cudaGetSymbolAddress((void**)&a_base, g_A);

    prologue_kernel<<<2080, 256>>>(x, ckw, ckb, cvw, cvb, rsk, rsv, W1, b1, W2, b2);

    for (int c = 0; c < NCHUNK; c++) {
        const float* Kc_p = nk_base + c * (CHUNK * DM);
        int has_prev = (c > 0);
        // stage1: fwd_c + kgram_c + recall-pred_{c-1}
        stage1_kernel<<<has_prev ? 1824 : 1040, 128>>>(Kc_p, 1, has_prev);
        // stage2: reduce1G_c + out-write_{c-1}
        stage2_kernel<<<has_prev ? 724 : 528, 256>>>(1, has_prev, c - 1, out);
        // pred_c: A@W2
        pred_gemm_kernel<<<784, 128>>>(a_base);
        reduce2_kernel<<<196, 256>>>(c);
        // dadh_c: dpred@W2^T
        dadh_gemm_kernel<<<784, 128>>>();
        reduceDh_kernel<<<512, 256>>>();
        // update_c + A2_c (Gram recall)
        update_recall_kernel<<<1069, 128>>>(Kc_p, wgt);
    }
    // epilogue: recall-pred_7 + out-write_7
    stage1_kernel<<<784, 128>>>(nk_base, 0, 1);
    stage2_kernel<<<196, 256>>>(0, 1, NCHUNK - 1, out);
}